// round 9
// baseline (speedup 1.0000x reference)
#include <cuda_runtime.h>
#include <cuda_bf16.h>
#include <math.h>
#include <stdint.h>

#define T_SEQ  2048
#define NFEAT  8192
#define NH     4
#define DV     256
#define HALF_N 4096   // NFEAT/2

// ---- device scratch (allocation-free rule: __device__ globals) ----
__device__ __nv_bfloat16 g_Qhi[(size_t)NH * T_SEQ * NFEAT];   // 134 MB
__device__ __nv_bfloat16 g_Qlo[(size_t)NH * T_SEQ * NFEAT];   // 134 MB
__device__ float         g_S [(size_t)NH * T_SEQ * T_SEQ];    // 67 MB
__device__ float2        g_tab[(size_t)T_SEQ * HALF_N];       // 67 MB cos/sin
__device__ double        g_freq[HALF_N];

// ============================================================================
// helpers
// ============================================================================
__device__ __forceinline__ unsigned smem_u32(const void* p) {
    return (unsigned)__cvta_generic_to_shared(p);
}
__device__ __forceinline__ void cp16(unsigned dst, const void* src) {
    asm volatile("cp.async.cg.shared.global [%0], [%1], 16;" :: "r"(dst), "l"(src));
}
#define CP_COMMIT() asm volatile("cp.async.commit_group;" ::: "memory")
#define CP_WAIT(n)  asm volatile("cp.async.wait_group %0;" :: "n"(n) : "memory")

__device__ __forceinline__ void ldsm4(unsigned& r0, unsigned& r1, unsigned& r2, unsigned& r3,
                                      unsigned addr) {
    asm volatile("ldmatrix.sync.aligned.m8n8.x4.shared.b16 {%0,%1,%2,%3}, [%4];"
                 : "=r"(r0), "=r"(r1), "=r"(r2), "=r"(r3) : "r"(addr));
}
__device__ __forceinline__ void mma_bf16(float* c, const unsigned* a, const unsigned* b) {
    asm volatile("mma.sync.aligned.m16n8k16.row.col.f32.bf16.bf16.f32 "
                 "{%0,%1,%2,%3}, {%4,%5,%6,%7}, {%8,%9}, {%0,%1,%2,%3};"
                 : "+f"(c[0]), "+f"(c[1]), "+f"(c[2]), "+f"(c[3])
                 : "r"(a[0]), "r"(a[1]), "r"(a[2]), "r"(a[3]), "r"(b[0]), "r"(b[1]));
}

// ============================================================================
// Kernel 0: per-pair frequency (fp64 exp2 hoisted)
// ============================================================================
__global__ void freq_kernel() {
    int p = blockIdx.x * 256 + threadIdx.x;
    if (p >= HALF_N) return;
    g_freq[p] = exp2(-(double)p * (1.0 / 256.0)) * (1.0 / (2.0 * M_PI));
}

// ============================================================================
// Kernel 1: cos/sin table. fp64 phase => exact mod-1; cospif/sinpif.
// ============================================================================
__global__ void build_tab_kernel() {
    int i = blockIdx.x * 256 + threadIdx.x;
    if (i >= T_SEQ * HALF_N) return;
    int t = i >> 12;
    int p = i & (HALF_N - 1);
    double phase = (double)t * g_freq[p];
    double fr    = phase - floor(phase);
    float  x     = (float)(2.0 * fr);
    g_tab[i] = make_float2(cospif(x), sinpif(x));
}

// ============================================================================
// Kernel 2: RoPE -> split bf16 (hi + lo)
// ============================================================================
__global__ void rope_kernel(const float* __restrict__ Q) {
    size_t i = (size_t)blockIdx.x * 256 + threadIdx.x;
    if (i >= (size_t)NH * T_SEQ * HALF_N) return;
    size_t r = i & ((size_t)T_SEQ * HALF_N - 1);
    float2 q  = ((const float2*)Q)[i];
    float2 cs = g_tab[r];
    float ox = q.x * cs.x - q.y * cs.y;
    float oy = q.y * cs.x + q.x * cs.y;
    __nv_bfloat16 hx = __float2bfloat16(ox);
    __nv_bfloat16 hy = __float2bfloat16(oy);
    float lx = ox - __bfloat162float(hx);
    float ly = oy - __bfloat162float(hy);
    __nv_bfloat162 h; h.x = hx; h.y = hy;
    __nv_bfloat162 l; l.x = __float2bfloat16(lx); l.y = __float2bfloat16(ly);
    ((__nv_bfloat162*)g_Qhi)[i] = h;
    ((__nv_bfloat162*)g_Qlo)[i] = l;
}

// ============================================================================
// Kernel 3: S = tril(QR*QR^T, k=-1) via split-bf16 HMMA, 3 passes (hh, h*lo, lo*h).
// 512 threads (16 warps, 4x4), 128x128 tile, 32x32 per-warp tile, BK=32,
// cp.async double-buffered smem, rows padded to 40 bf16 (80 B).
// ============================================================================
#define BK        32
#define LDS_PAD   40
#define ARRB      (128 * LDS_PAD * 2)      // 10240
#define BUFB      (4 * ARRB)               // 40960 (Ahi, Alo, Bhi, Blo)
#define SMEM_BYTES (2 * BUFB)              // 81920

#define OFF_AHI 0
#define OFF_ALO (1 * ARRB)
#define OFF_BHI (2 * ARRB)
#define OFF_BLO (3 * ARRB)

__global__ __launch_bounds__(512, 1) void gemm_scores_kernel() {
    extern __shared__ __align__(128) char smem[];
    const unsigned sbase = smem_u32(smem);

    const int h = blockIdx.y;
    const __nv_bfloat16* __restrict__ Qhi = g_Qhi + (size_t)h * T_SEQ * NFEAT;
    const __nv_bfloat16* __restrict__ Qlo = g_Qlo + (size_t)h * T_SEQ * NFEAT;
    float* __restrict__ Sh = g_S + (size_t)h * T_SEQ * T_SEQ;

    // lower-triangular tile decode
    int lt = blockIdx.x;
    int bi = (int)((sqrtf(8.0f * (float)lt + 1.0f) - 1.0f) * 0.5f);
    while ((bi + 1) * (bi + 2) / 2 <= lt) ++bi;
    while (bi * (bi + 1) / 2 > lt)        --bi;
    const int bj = lt - bi * (bi + 1) / 2;

    const int tid  = threadIdx.x;
    const int lane = tid & 31;
    const int wid  = tid >> 5;
    const int wm   = wid >> 2;   // 0..3 (row group of 32)
    const int wn   = wid & 3;    // 0..3 (col group of 32)

    // ---- global-load mapping: 1 x 16B chunk per thread per array per stage ----
    const int grow = tid >> 2;          // 0..127
    const int gc16 = tid & 3;           // 0..3 (16B units within 64B row-chunk)
    const __nv_bfloat16* gsrc[4];
    gsrc[0] = Qhi + (size_t)(bi * 128 + grow) * NFEAT + gc16 * 8;
    gsrc[1] = Qlo + (size_t)(bi * 128 + grow) * NFEAT + gc16 * 8;
    gsrc[2] = Qhi + (size_t)(bj * 128 + grow) * NFEAT + gc16 * 8;
    gsrc[3] = Qlo + (size_t)(bj * 128 + grow) * NFEAT + gc16 * 8;
    const unsigned sdst = (unsigned)(grow * (LDS_PAD * 2) + gc16 * 16);

    // ---- ldmatrix lane offsets ----
    const int g  = lane >> 3;            // matrix id 0..3
    const int rr = lane & 7;
    const int acol = (g >> 1) * 8;       // + kk
    unsigned a_off[2];
#pragma unroll
    for (int mt = 0; mt < 2; ++mt) {
        int arow = wm * 32 + mt * 16 + rr + (g & 1) * 8;
        a_off[mt] = (unsigned)(arow * (LDS_PAD * 2) + acol * 2);
    }
    unsigned b_off[2];
#pragma unroll
    for (int np = 0; np < 2; ++np) {
        int brow = wn * 32 + np * 16 + rr + (g & 1) * 8;
        b_off[np] = (unsigned)(brow * (LDS_PAD * 2) + acol * 2);
    }

    float acc[2][4][4];
#pragma unroll
    for (int i = 0; i < 2; ++i)
#pragma unroll
        for (int j = 0; j < 4; ++j)
#pragma unroll
            for (int k = 0; k < 4; ++k) acc[i][j][k] = 0.0f;

    // ---- prologue: stage 0 ----
#pragma unroll
    for (int arr = 0; arr < 4; ++arr)
        cp16(sbase + arr * ARRB + sdst, gsrc[arr]);
    CP_COMMIT();

    const int NKC = NFEAT / BK;   // 256
    for (int kc = 0; kc < NKC; ++kc) {
        const unsigned buf = sbase + (kc & 1) * BUFB;
        if (kc + 1 < NKC) {
            const unsigned nbuf = sbase + ((kc + 1) & 1) * BUFB;
            const size_t o = (size_t)(kc + 1) * BK;
#pragma unroll
            for (int arr = 0; arr < 4; ++arr)
                cp16(nbuf + arr * ARRB + sdst, gsrc[arr] + o);
            CP_COMMIT();
            CP_WAIT(1);
        } else {
            CP_WAIT(0);
        }
        __syncthreads();

#pragma unroll
        for (int kk = 0; kk < BK; kk += 16) {
            unsigned ahi[2][4], alo[2][4], bhi[4][2], blo[4][2];
#pragma unroll
            for (int mt = 0; mt < 2; ++mt)
                ldsm4(ahi[mt][0], ahi[mt][1], ahi[mt][2], ahi[mt][3],
                      buf + OFF_AHI + a_off[mt] + kk * 2);
#pragma unroll
            for (int np = 0; np < 2; ++np) {
                unsigned f0, f1, f2, f3;
                ldsm4(f0, f1, f2, f3, buf + OFF_BHI + b_off[np] + kk * 2);
                bhi[2 * np][0] = f0; bhi[2 * np][1] = f2;
                bhi[2 * np + 1][0] = f1; bhi[2 * np + 1][1] = f3;
                ldsm4(f0, f1, f2, f3, buf + OFF_BLO + b_off[np] + kk * 2);
                blo[2 * np][0] = f0; blo[2 * np][1] = f2;
                blo[2 * np + 1][0] = f1; blo[2 * np + 1][1] = f3;
            }
#pragma unroll
            for (int mt = 0; mt < 2; ++mt)
                ldsm4(alo[mt][0], alo[mt][1], alo[mt][2], alo[mt][3],
                      buf + OFF_ALO + a_off[mt] + kk * 2);

#pragma unroll
            for (int mt = 0; mt < 2; ++mt)
#pragma unroll
                for (int nt = 0; nt < 4; ++nt)
                    mma_bf16(acc[mt][nt], ahi[mt], bhi[nt]);
#pragma unroll
            for (int mt = 0; mt < 2; ++mt)
#pragma unroll
                for (int nt = 0; nt < 4; ++nt)
                    mma_bf16(acc[mt][nt], ahi[mt], blo[nt]);
#pragma unroll
            for (int mt = 0; mt < 2; ++mt)
#pragma unroll
                for (int nt = 0; nt < 4; ++nt)
                    mma_bf16(acc[mt][nt], alo[mt], bhi[nt]);
        }
        __syncthreads();
    }

    // ---- writeback with strict-lower mask on diagonal tiles ----
    const bool diag = (bi == bj);
    const int qrow = lane >> 2;
    const int qcol = (lane & 3) * 2;
#pragma unroll
    for (int mt = 0; mt < 2; ++mt) {
#pragma unroll
        for (int nt = 0; nt < 4; ++nt) {
            int row = bi * 128 + wm * 32 + mt * 16 + qrow;
            int col = bj * 128 + wn * 32 + nt * 8 + qcol;
#pragma unroll
            for (int half = 0; half < 2; ++half) {
                int r = row + half * 8;
                float v0 = acc[mt][nt][half * 2 + 0];
                float v1 = acc[mt][nt][half * 2 + 1];
                if (diag) {
                    if (col + 0 >= r) v0 = 0.0f;
                    if (col + 1 >= r) v1 = 0.0f;
                }
                *(float2*)(Sh + (size_t)r * T_SEQ + col) = make_float2(v0, v1);
            }
        }
    }
}

// ============================================================================
// Kernel 4: out = S * V per head, reading only tiles kt <= bi (fp32 SIMT).
// ============================================================================
__global__ __launch_bounds__(256, 2) void gemm_out_kernel(const float* __restrict__ V,
                                                          float* __restrict__ O) {
    const int h  = blockIdx.z;
    const int bi = blockIdx.y;
    const int bj = blockIdx.x;
    const float* __restrict__ Sh = g_S + (size_t)h * T_SEQ * T_SEQ;
    float* __restrict__ Oh = O + (size_t)h * T_SEQ * DV;

    __shared__ float As[2][8][132];
    __shared__ float Bs[2][8][132];

    const int tid  = threadIdx.x;
    const int lrow = tid >> 1;
    const int c4   = (tid & 1) * 4;
    const float* ga = Sh + (size_t)(bi * 128 + lrow) * T_SEQ + c4;

    const int vrow = tid >> 5;
    const int vcol = (tid & 31) * 4;
    const float* gv = V + (size_t)vrow * DV + bj * 128 + vcol;

    const int tx = tid & 15, ty = tid >> 4;

    float acc[8][8];
#pragma unroll
    for (int i = 0; i < 8; ++i)
#pragma unroll
        for (int j = 0; j < 8; ++j) acc[i][j] = 0.0f;

    {
        float4 ra = *(const float4*)ga;
        float4 rv = *(const float4*)gv;
        As[0][c4 + 0][lrow] = ra.x; As[0][c4 + 1][lrow] = ra.y;
        As[0][c4 + 2][lrow] = ra.z; As[0][c4 + 3][lrow] = ra.w;
        *(float4*)&Bs[0][vrow][vcol] = rv;
    }
    __syncthreads();

    const int NK = (bi + 1) * 16;
    int buf = 0;
    for (int kc = 0; kc < NK; ++kc) {
        float4 na, nv;
        if (kc + 1 < NK) {
            na = *(const float4*)(ga + (size_t)(kc + 1) * 8);
            nv = *(const float4*)(gv + (size_t)(kc + 1) * 8 * DV);
        }
#pragma unroll
        for (int k = 0; k < 8; ++k) {
            float4 a0 = *(const float4*)&As[buf][k][ty * 8];
            float4 a1 = *(const float4*)&As[buf][k][ty * 8 + 4];
            float4 b0 = *(const float4*)&Bs[buf][k][tx * 8];
            float4 b1 = *(const float4*)&Bs[buf][k][tx * 8 + 4];
            float a[8] = {a0.x, a0.y, a0.z, a0.w, a1.x, a1.y, a1.z, a1.w};
            float b[8] = {b0.x, b0.y, b0.z, b0.w, b1.x, b1.y, b1.z, b1.w};
#pragma unroll
            for (int i = 0; i < 8; ++i)
#pragma unroll
                for (int j = 0; j < 8; ++j)
                    acc[i][j] = fmaf(a[i], b[j], acc[i][j]);
        }
        if (kc + 1 < NK) {
            int nb2 = buf ^ 1;
            As[nb2][c4 + 0][lrow] = na.x; As[nb2][c4 + 1][lrow] = na.y;
            As[nb2][c4 + 2][lrow] = na.z; As[nb2][c4 + 3][lrow] = na.w;
            *(float4*)&Bs[nb2][vrow][vcol] = nv;
        }
        __syncthreads();
        buf ^= 1;
    }

    const int row0 = bi * 128 + ty * 8;
    const int col0 = bj * 128 + tx * 8;
#pragma unroll
    for (int i = 0; i < 8; ++i) {
        float* dst = Oh + (size_t)(row0 + i) * DV + col0;
        *(float4*)(dst)     = make_float4(acc[i][0], acc[i][1], acc[i][2], acc[i][3]);
        *(float4*)(dst + 4) = make_float4(acc[i][4], acc[i][5], acc[i][6], acc[i][7]);
    }
}

// ============================================================================
extern "C" void kernel_launch(void* const* d_in, const int* in_sizes, int n_in,
                              void* d_out, int out_size) {
    const float* Q = (const float*)d_in[0];
    const float* V = (const float*)d_in[1];
    float* O = (float*)d_out;

    static bool attr_set = false;
    if (!attr_set) {
        cudaFuncSetAttribute(gemm_scores_kernel,
                             cudaFuncAttributeMaxDynamicSharedMemorySize, SMEM_BYTES);
        attr_set = true;
    }

    const int tab_elems  = T_SEQ * HALF_N;
    const int rope_pairs = NH * T_SEQ * HALF_N;

    freq_kernel<<<(HALF_N + 255) / 256, 256>>>();
    build_tab_kernel<<<(tab_elems + 255) / 256, 256>>>();
    rope_kernel<<<(rope_pairs + 255) / 256, 256>>>(Q);
    gemm_scores_kernel<<<dim3(136, NH), 512, SMEM_BYTES>>>();
    gemm_out_kernel<<<dim3(DV / 128, T_SEQ / 128, NH), 256>>>(V, O);
}

// round 11
// speedup vs baseline: 1.0078x; 1.0078x over previous
#include <cuda_runtime.h>
#include <cuda_bf16.h>
#include <math.h>
#include <stdint.h>

#define T_SEQ  2048
#define NFEAT  8192
#define NH     4
#define DV     256
#define HALF_N 4096   // NFEAT/2

// ---- device scratch (allocation-free rule: __device__ globals) ----
__device__ __nv_bfloat16 g_Qhi[(size_t)NH * T_SEQ * NFEAT];   // 134 MB
__device__ __nv_bfloat16 g_Qlo[(size_t)NH * T_SEQ * NFEAT];   // 134 MB
__device__ float         g_S [(size_t)NH * T_SEQ * T_SEQ];    // 67 MB
__device__ float2        g_tab[(size_t)T_SEQ * HALF_N];       // 67 MB cos/sin
__device__ double        g_freq[HALF_N];

// ============================================================================
// helpers
// ============================================================================
__device__ __forceinline__ unsigned smem_u32(const void* p) {
    return (unsigned)__cvta_generic_to_shared(p);
}
__device__ __forceinline__ void cp16(unsigned dst, const void* src) {
    asm volatile("cp.async.cg.shared.global [%0], [%1], 16;" :: "r"(dst), "l"(src));
}
#define CP_COMMIT() asm volatile("cp.async.commit_group;" ::: "memory")
#define CP_WAIT(n)  asm volatile("cp.async.wait_group %0;" :: "n"(n) : "memory")

__device__ __forceinline__ void ldsm4(unsigned& r0, unsigned& r1, unsigned& r2, unsigned& r3,
                                      unsigned addr) {
    asm volatile("ldmatrix.sync.aligned.m8n8.x4.shared.b16 {%0,%1,%2,%3}, [%4];"
                 : "=r"(r0), "=r"(r1), "=r"(r2), "=r"(r3) : "r"(addr));
}
__device__ __forceinline__ void mma_bf16(float* c, const unsigned* a, const unsigned* b) {
    asm volatile("mma.sync.aligned.m16n8k16.row.col.f32.bf16.bf16.f32 "
                 "{%0,%1,%2,%3}, {%4,%5,%6,%7}, {%8,%9}, {%0,%1,%2,%3};"
                 : "+f"(c[0]), "+f"(c[1]), "+f"(c[2]), "+f"(c[3])
                 : "r"(a[0]), "r"(a[1]), "r"(a[2]), "r"(a[3]), "r"(b[0]), "r"(b[1]));
}

// ============================================================================
// Kernel 0: per-pair frequency (fp64 exp2 hoisted)
// ============================================================================
__global__ void freq_kernel() {
    int p = blockIdx.x * 256 + threadIdx.x;
    if (p >= HALF_N) return;
    g_freq[p] = exp2(-(double)p * (1.0 / 256.0)) * (1.0 / (2.0 * M_PI));
}

// ============================================================================
// Kernel 1: cos/sin table. fp64 phase => exact mod-1; cospif/sinpif.
// ============================================================================
__global__ void build_tab_kernel() {
    int i = blockIdx.x * 256 + threadIdx.x;
    if (i >= T_SEQ * HALF_N) return;
    int t = i >> 12;
    int p = i & (HALF_N - 1);
    double phase = (double)t * g_freq[p];
    double fr    = phase - floor(phase);
    float  x     = (float)(2.0 * fr);
    g_tab[i] = make_float2(cospif(x), sinpif(x));
}

// ============================================================================
// Kernel 2: RoPE -> split bf16 (hi + lo)
// ============================================================================
__global__ void rope_kernel(const float* __restrict__ Q) {
    size_t i = (size_t)blockIdx.x * 256 + threadIdx.x;
    if (i >= (size_t)NH * T_SEQ * HALF_N) return;
    size_t r = i & ((size_t)T_SEQ * HALF_N - 1);
    float2 q  = ((const float2*)Q)[i];
    float2 cs = g_tab[r];
    float ox = q.x * cs.x - q.y * cs.y;
    float oy = q.y * cs.x + q.x * cs.y;
    __nv_bfloat16 hx = __float2bfloat16(ox);
    __nv_bfloat16 hy = __float2bfloat16(oy);
    float lx = ox - __bfloat162float(hx);
    float ly = oy - __bfloat162float(hy);
    __nv_bfloat162 h; h.x = hx; h.y = hy;
    __nv_bfloat162 l; l.x = __float2bfloat16(lx); l.y = __float2bfloat16(ly);
    ((__nv_bfloat162*)g_Qhi)[i] = h;
    ((__nv_bfloat162*)g_Qlo)[i] = l;
}

// ============================================================================
// Kernel 3: S = tril(QR*QR^T, k=-1), split-bf16 HMMA (hh, h*lo, lo*h).
// 256 threads (8 warps, 2m x 4n of 64x32), 128x128 tile, BK=32,
// 3-stage cp.async pipeline, one __syncthreads per chunk.
// smem rows padded to 40 bf16 (80 B) -> conflict-free ldmatrix.
// ============================================================================
#define BK        32
#define LDS_PAD   40
#define ARRB      (128 * LDS_PAD * 2)      // 10240
#define STAGEB    (4 * ARRB)               // 40960 (Ahi, Alo, Bhi, Blo)
#define NSTAGE    3
#define SMEM_BYTES (NSTAGE * STAGEB)       // 122880

#define OFF_AHI 0
#define OFF_ALO (1 * ARRB)
#define OFF_BHI (2 * ARRB)
#define OFF_BLO (3 * ARRB)

__global__ __launch_bounds__(256, 1) void gemm_scores_kernel() {
    extern __shared__ __align__(128) char smem[];
    const unsigned sbase = smem_u32(smem);

    const int h = blockIdx.y;
    const __nv_bfloat16* __restrict__ Qhi = g_Qhi + (size_t)h * T_SEQ * NFEAT;
    const __nv_bfloat16* __restrict__ Qlo = g_Qlo + (size_t)h * T_SEQ * NFEAT;
    float* __restrict__ Sh = g_S + (size_t)h * T_SEQ * T_SEQ;

    // lower-triangular tile decode
    int lt = blockIdx.x;
    int bi = (int)((sqrtf(8.0f * (float)lt + 1.0f) - 1.0f) * 0.5f);
    while ((bi + 1) * (bi + 2) / 2 <= lt) ++bi;
    while (bi * (bi + 1) / 2 > lt)        --bi;
    const int bj = lt - bi * (bi + 1) / 2;

    const int tid  = threadIdx.x;
    const int lane = tid & 31;
    const int wid  = tid >> 5;
    const int wm   = wid >> 2;   // 0..1
    const int wn   = wid & 3;    // 0..3

    // ---- global-load mapping: 8 x 16B cp.async per thread per stage ----
    // 2048 chunks/stage: arr = idx>>9, row = (idx&511)>>2, c16 = idx&3
    const __nv_bfloat16* srcA[4];
    srcA[0] = Qhi + (size_t)(bi * 128) * NFEAT;
    srcA[1] = Qlo + (size_t)(bi * 128) * NFEAT;
    srcA[2] = Qhi + (size_t)(bj * 128) * NFEAT;
    srcA[3] = Qlo + (size_t)(bj * 128) * NFEAT;

    // per-thread fixed part: for j in 0..7, idx = j*256+tid
    // arr(j) = (j*256+tid)>>9  -> arr = (j>>1) since tid<256: idx in [j*256, j*256+255]
    // j even: idx 256j..256j+255 -> arr = j/2, rem = tid (tid<256 -> rem<512 half)
    // Precompute rows/cols per j:
    unsigned sdst[8];
    const __nv_bfloat16* gsrc[8];
#pragma unroll
    for (int j = 0; j < 8; ++j) {
        int idx = j * 256 + tid;
        int arr = idx >> 9;
        int rem = idx & 511;
        int row = rem >> 2;
        int c16 = rem & 3;
        sdst[j] = (unsigned)(arr * ARRB + row * (LDS_PAD * 2) + c16 * 16);
        gsrc[j] = srcA[arr] + (size_t)row * NFEAT + c16 * 8;
    }

    // ---- ldmatrix lane offsets (R2 layout: 64x32 per warp) ----
    const int g  = lane >> 3;
    const int rr = lane & 7;
    const int arow = wm * 64 + rr + (g & 1) * 8;
    const int acol = (g >> 1) * 8;
    unsigned a_off[4];
#pragma unroll
    for (int mt = 0; mt < 4; ++mt)
        a_off[mt] = (unsigned)((arow + mt * 16) * (LDS_PAD * 2) + acol * 2);
    unsigned b_off[2];
#pragma unroll
    for (int np = 0; np < 2; ++np) {
        int brow = wn * 32 + np * 16 + rr + (g & 1) * 8;
        b_off[np] = (unsigned)(brow * (LDS_PAD * 2) + acol * 2);
    }

    float acc[4][4][4];
#pragma unroll
    for (int i = 0; i < 4; ++i)
#pragma unroll
        for (int j = 0; j < 4; ++j)
#pragma unroll
            for (int k = 0; k < 4; ++k) acc[i][j][k] = 0.0f;

    const int NKC = NFEAT / BK;   // 256

    // ---- prologue: stages 0,1 ----
#pragma unroll
    for (int s = 0; s < 2; ++s) {
        const unsigned sb = sbase + s * STAGEB;
        const size_t o = (size_t)s * BK;
#pragma unroll
        for (int j = 0; j < 8; ++j)
            cp16(sb + sdst[j], gsrc[j] + o);
        CP_COMMIT();
    }

    int bufidx = 0;   // stage slot of chunk kc
    for (int kc = 0; kc < NKC; ++kc) {
        // wait for chunk kc (pending groups after wait: the ones behind it)
        if (kc + 1 < NKC) { CP_WAIT(1); } else { CP_WAIT(0); }
        __syncthreads();   // all warps see buf[kc] ready AND are done with buf[kc-1]

        // issue load for chunk kc+2 into the slot freed by chunk kc-1
        if (kc + 2 < NKC) {
            int ns = bufidx + 2; if (ns >= NSTAGE) ns -= NSTAGE;
            const unsigned sb = sbase + ns * STAGEB;
            const size_t o = (size_t)(kc + 2) * BK;
#pragma unroll
            for (int j = 0; j < 8; ++j)
                cp16(sb + sdst[j], gsrc[j] + o);
            CP_COMMIT();
        }

        const unsigned buf = sbase + bufidx * STAGEB;
#pragma unroll
        for (int kk = 0; kk < BK; kk += 16) {
            unsigned ahi[4][4], alo[4][4], bhi[4][2], blo[4][2];
#pragma unroll
            for (int mt = 0; mt < 4; ++mt)
                ldsm4(ahi[mt][0], ahi[mt][1], ahi[mt][2], ahi[mt][3],
                      buf + OFF_AHI + a_off[mt] + kk * 2);
#pragma unroll
            for (int np = 0; np < 2; ++np) {
                unsigned f0, f1, f2, f3;
                ldsm4(f0, f1, f2, f3, buf + OFF_BHI + b_off[np] + kk * 2);
                bhi[2 * np][0] = f0; bhi[2 * np][1] = f2;
                bhi[2 * np + 1][0] = f1; bhi[2 * np + 1][1] = f3;
                ldsm4(f0, f1, f2, f3, buf + OFF_BLO + b_off[np] + kk * 2);
                blo[2 * np][0] = f0; blo[2 * np][1] = f2;
                blo[2 * np + 1][0] = f1; blo[2 * np + 1][1] = f3;
            }
#pragma unroll
            for (int mt = 0; mt < 4; ++mt)
                ldsm4(alo[mt][0], alo[mt][1], alo[mt][2], alo[mt][3],
                      buf + OFF_ALO + a_off[mt] + kk * 2);

#pragma unroll
            for (int mt = 0; mt < 4; ++mt)
#pragma unroll
                for (int nt = 0; nt < 4; ++nt)
                    mma_bf16(acc[mt][nt], ahi[mt], bhi[nt]);
#pragma unroll
            for (int mt = 0; mt < 4; ++mt)
#pragma unroll
                for (int nt = 0; nt < 4; ++nt)
                    mma_bf16(acc[mt][nt], ahi[mt], blo[nt]);
#pragma unroll
            for (int mt = 0; mt < 4; ++mt)
#pragma unroll
                for (int nt = 0; nt < 4; ++nt)
                    mma_bf16(acc[mt][nt], alo[mt], bhi[nt]);
        }

        ++bufidx; if (bufidx == NSTAGE) bufidx = 0;
    }

    // ---- writeback with strict-lower mask on diagonal tiles ----
    const bool diag = (bi == bj);
    const int qrow = lane >> 2;
    const int qcol = (lane & 3) * 2;
#pragma unroll
    for (int mt = 0; mt < 4; ++mt) {
#pragma unroll
        for (int nt = 0; nt < 4; ++nt) {
            int row = bi * 128 + wm * 64 + mt * 16 + qrow;
            int col = bj * 128 + wn * 32 + nt * 8 + qcol;
#pragma unroll
            for (int half = 0; half < 2; ++half) {
                int r = row + half * 8;
                float v0 = acc[mt][nt][half * 2 + 0];
                float v1 = acc[mt][nt][half * 2 + 1];
                if (diag) {
                    if (col + 0 >= r) v0 = 0.0f;
                    if (col + 1 >= r) v1 = 0.0f;
                }
                *(float2*)(Sh + (size_t)r * T_SEQ + col) = make_float2(v0, v1);
            }
        }
    }
}

// ============================================================================
// Kernel 4: out = S * V per head, reading only tiles kt <= bi (fp32 SIMT).
// ============================================================================
__global__ __launch_bounds__(256, 2) void gemm_out_kernel(const float* __restrict__ V,
                                                          float* __restrict__ O) {
    const int h  = blockIdx.z;
    const int bi = blockIdx.y;
    const int bj = blockIdx.x;
    const float* __restrict__ Sh = g_S + (size_t)h * T_SEQ * T_SEQ;
    float* __restrict__ Oh = O + (size_t)h * T_SEQ * DV;

    __shared__ float As[2][8][132];
    __shared__ float Bs[2][8][132];

    const int tid  = threadIdx.x;
    const int lrow = tid >> 1;
    const int c4   = (tid & 1) * 4;
    const float* ga = Sh + (size_t)(bi * 128 + lrow) * T_SEQ + c4;

    const int vrow = tid >> 5;
    const int vcol = (tid & 31) * 4;
    const float* gv = V + (size_t)vrow * DV + bj * 128 + vcol;

    const int tx = tid & 15, ty = tid >> 4;

    float acc[8][8];
#pragma unroll
    for (int i = 0; i < 8; ++i)
#pragma unroll
        for (int j = 0; j < 8; ++j) acc[i][j] = 0.0f;

    {
        float4 ra = *(const float4*)ga;
        float4 rv = *(const float4*)gv;
        As[0][c4 + 0][lrow] = ra.x; As[0][c4 + 1][lrow] = ra.y;
        As[0][c4 + 2][lrow] = ra.z; As[0][c4 + 3][lrow] = ra.w;
        *(float4*)&Bs[0][vrow][vcol] = rv;
    }
    __syncthreads();

    const int NK = (bi + 1) * 16;
    int buf = 0;
    for (int kc = 0; kc < NK; ++kc) {
        float4 na, nv;
        if (kc + 1 < NK) {
            na = *(const float4*)(ga + (size_t)(kc + 1) * 8);
            nv = *(const float4*)(gv + (size_t)(kc + 1) * 8 * DV);
        }
#pragma unroll
        for (int k = 0; k < 8; ++k) {
            float4 a0 = *(const float4*)&As[buf][k][ty * 8];
            float4 a1 = *(const float4*)&As[buf][k][ty * 8 + 4];
            float4 b0 = *(const float4*)&Bs[buf][k][tx * 8];
            float4 b1 = *(const float4*)&Bs[buf][k][tx * 8 + 4];
            float a[8] = {a0.x, a0.y, a0.z, a0.w, a1.x, a1.y, a1.z, a1.w};
            float b[8] = {b0.x, b0.y, b0.z, b0.w, b1.x, b1.y, b1.z, b1.w};
#pragma unroll
            for (int i = 0; i < 8; ++i)
#pragma unroll
                for (int j = 0; j < 8; ++j)
                    acc[i][j] = fmaf(a[i], b[j], acc[i][j]);
        }
        if (kc + 1 < NK) {
            int nb2 = buf ^ 1;
            As[nb2][c4 + 0][lrow] = na.x; As[nb2][c4 + 1][lrow] = na.y;
            As[nb2][c4 + 2][lrow] = na.z; As[nb2][c4 + 3][lrow] = na.w;
            *(float4*)&Bs[nb2][vrow][vcol] = nv;
        }
        __syncthreads();
        buf ^= 1;
    }

    const int row0 = bi * 128 + ty * 8;
    const int col0 = bj * 128 + tx * 8;
#pragma unroll
    for (int i = 0; i < 8; ++i) {
        float* dst = Oh + (size_t)(row0 + i) * DV + col0;
        *(float4*)(dst)     = make_float4(acc[i][0], acc[i][1], acc[i][2], acc[i][3]);
        *(float4*)(dst + 4) = make_float4(acc[i][4], acc[i][5], acc[i][6], acc[i][7]);
    }
}

// ============================================================================
extern "C" void kernel_launch(void* const* d_in, const int* in_sizes, int n_in,
                              void* d_out, int out_size) {
    const float* Q = (const float*)d_in[0];
    const float* V = (const float*)d_in[1];
    float* O = (float*)d_out;

    static bool attr_set = false;
    if (!attr_set) {
        cudaFuncSetAttribute(gemm_scores_kernel,
                             cudaFuncAttributeMaxDynamicSharedMemorySize, SMEM_BYTES);
        attr_set = true;
    }

    const int tab_elems  = T_SEQ * HALF_N;
    const int rope_pairs = NH * T_SEQ * HALF_N;

    freq_kernel<<<(HALF_N + 255) / 256, 256>>>();
    build_tab_kernel<<<(tab_elems + 255) / 256, 256>>>();
    rope_kernel<<<(rope_pairs + 255) / 256, 256>>>(Q);
    gemm_scores_kernel<<<dim3(136, NH), 256, SMEM_BYTES>>>();
    gemm_out_kernel<<<dim3(DV / 128, T_SEQ / 128, NH), 256>>>(V, O);
}

// round 13
// speedup vs baseline: 1.1024x; 1.0939x over previous
#include <cuda_runtime.h>
#include <cuda_bf16.h>
#include <math.h>
#include <stdint.h>

#define T_SEQ  2048
#define NFEAT  8192
#define NH     4
#define DV     256
#define HALF_N 4096   // NFEAT/2

// ---- device scratch (allocation-free rule: __device__ globals) ----
__device__ __nv_bfloat16 g_Qhi[(size_t)NH * T_SEQ * NFEAT];   // 134 MB
__device__ __nv_bfloat16 g_Qlo[(size_t)NH * T_SEQ * NFEAT];   // 134 MB
__device__ float         g_S [(size_t)NH * T_SEQ * T_SEQ];    // 67 MB
__device__ float2        g_tab[(size_t)T_SEQ * HALF_N];       // 67 MB cos/sin
__device__ double        g_freq[HALF_N];

// ============================================================================
// helpers
// ============================================================================
__device__ __forceinline__ unsigned smem_u32(const void* p) {
    return (unsigned)__cvta_generic_to_shared(p);
}
__device__ __forceinline__ void cp16(unsigned dst, const void* src) {
    asm volatile("cp.async.cg.shared.global [%0], [%1], 16;" :: "r"(dst), "l"(src));
}
#define CP_COMMIT() asm volatile("cp.async.commit_group;" ::: "memory")
#define CP_WAIT(n)  asm volatile("cp.async.wait_group %0;" :: "n"(n) : "memory")

__device__ __forceinline__ void ldsm4(unsigned& r0, unsigned& r1, unsigned& r2, unsigned& r3,
                                      unsigned addr) {
    asm volatile("ldmatrix.sync.aligned.m8n8.x4.shared.b16 {%0,%1,%2,%3}, [%4];"
                 : "=r"(r0), "=r"(r1), "=r"(r2), "=r"(r3) : "r"(addr));
}
__device__ __forceinline__ void mma_bf16(float* c, const unsigned* a, const unsigned* b) {
    asm volatile("mma.sync.aligned.m16n8k16.row.col.f32.bf16.bf16.f32 "
                 "{%0,%1,%2,%3}, {%4,%5,%6,%7}, {%8,%9}, {%0,%1,%2,%3};"
                 : "+f"(c[0]), "+f"(c[1]), "+f"(c[2]), "+f"(c[3])
                 : "r"(a[0]), "r"(a[1]), "r"(a[2]), "r"(a[3]), "r"(b[0]), "r"(b[1]));
}

// ============================================================================
// Kernel 0: per-pair frequency (fp64 exp2 hoisted)
// ============================================================================
__global__ void freq_kernel() {
    int p = blockIdx.x * 256 + threadIdx.x;
    if (p >= HALF_N) return;
    g_freq[p] = exp2(-(double)p * (1.0 / 256.0)) * (1.0 / (2.0 * M_PI));
}

// ============================================================================
// Kernel 1: cos/sin table. fp64 phase => exact mod-1; cospif/sinpif.
// ============================================================================
__global__ void build_tab_kernel() {
    int i = blockIdx.x * 256 + threadIdx.x;
    if (i >= T_SEQ * HALF_N) return;
    int t = i >> 12;
    int p = i & (HALF_N - 1);
    double phase = (double)t * g_freq[p];
    double fr    = phase - floor(phase);
    float  x     = (float)(2.0 * fr);
    g_tab[i] = make_float2(cospif(x), sinpif(x));
}

// ============================================================================
// Kernel 2: RoPE -> split bf16 (hi + lo)
// ============================================================================
__global__ void rope_kernel(const float* __restrict__ Q) {
    size_t i = (size_t)blockIdx.x * 256 + threadIdx.x;
    if (i >= (size_t)NH * T_SEQ * HALF_N) return;
    size_t r = i & ((size_t)T_SEQ * HALF_N - 1);
    float2 q  = ((const float2*)Q)[i];
    float2 cs = g_tab[r];
    float ox = q.x * cs.x - q.y * cs.y;
    float oy = q.y * cs.x + q.x * cs.y;
    __nv_bfloat16 hx = __float2bfloat16(ox);
    __nv_bfloat16 hy = __float2bfloat16(oy);
    float lx = ox - __bfloat162float(hx);
    float ly = oy - __bfloat162float(hy);
    __nv_bfloat162 h; h.x = hx; h.y = hy;
    __nv_bfloat162 l; l.x = __float2bfloat16(lx); l.y = __float2bfloat16(ly);
    ((__nv_bfloat162*)g_Qhi)[i] = h;
    ((__nv_bfloat162*)g_Qlo)[i] = l;
}

// ============================================================================
// Kernel 3: S = tril(QR*QR^T, k=-1), split-bf16 HMMA (hh, h*lo, lo*h).
// 256 threads (8 warps, 2m x 4n of 64x32), 128x128 tile, BK=32,
// cp.async double-buffer, ONE barrier per chunk, loads issued post-barrier.
// __launch_bounds__(256, 2): regs<=128 so 2 CTAs co-reside per SM.
// ============================================================================
#define BK        32
#define LDS_PAD   40
#define ARRB      (128 * LDS_PAD * 2)      // 10240
#define STAGEB    (4 * ARRB)               // 40960 (Ahi, Alo, Bhi, Blo)
#define SMEM_BYTES (2 * STAGEB)            // 81920

#define OFF_AHI 0
#define OFF_ALO (1 * ARRB)
#define OFF_BHI (2 * ARRB)
#define OFF_BLO (3 * ARRB)

__global__ __launch_bounds__(256, 2) void gemm_scores_kernel() {
    extern __shared__ __align__(128) char smem[];
    const unsigned sbase = smem_u32(smem);

    const int h = blockIdx.y;
    const __nv_bfloat16* __restrict__ Qhi = g_Qhi + (size_t)h * T_SEQ * NFEAT;
    const __nv_bfloat16* __restrict__ Qlo = g_Qlo + (size_t)h * T_SEQ * NFEAT;
    float* __restrict__ Sh = g_S + (size_t)h * T_SEQ * T_SEQ;

    // lower-triangular tile decode
    int lt = blockIdx.x;
    int bi = (int)((sqrtf(8.0f * (float)lt + 1.0f) - 1.0f) * 0.5f);
    while ((bi + 1) * (bi + 2) / 2 <= lt) ++bi;
    while (bi * (bi + 1) / 2 > lt)        --bi;
    const int bj = lt - bi * (bi + 1) / 2;

    const int tid  = threadIdx.x;
    const int lane = tid & 31;
    const int wid  = tid >> 5;
    const int wm   = wid >> 2;   // 0..1
    const int wn   = wid & 3;    // 0..3

    // ---- global-load mapping: 8 x 16B cp.async per thread per stage ----
    const __nv_bfloat16* srcA[4];
    srcA[0] = Qhi + (size_t)(bi * 128) * NFEAT;
    srcA[1] = Qlo + (size_t)(bi * 128) * NFEAT;
    srcA[2] = Qhi + (size_t)(bj * 128) * NFEAT;
    srcA[3] = Qlo + (size_t)(bj * 128) * NFEAT;

    unsigned sdst[8];
    const __nv_bfloat16* gsrc[8];
#pragma unroll
    for (int j = 0; j < 8; ++j) {
        int idx = j * 256 + tid;
        int arr = idx >> 9;
        int rem = idx & 511;
        int row = rem >> 2;
        int c16 = rem & 3;
        sdst[j] = (unsigned)(arr * ARRB + row * (LDS_PAD * 2) + c16 * 16);
        gsrc[j] = srcA[arr] + (size_t)row * NFEAT + c16 * 8;
    }

    // ---- ldmatrix lane offsets (64x32 per warp) ----
    const int g  = lane >> 3;
    const int rr = lane & 7;
    const int arow = wm * 64 + rr + (g & 1) * 8;
    const int acol = (g >> 1) * 8;
    unsigned a_off[4];
#pragma unroll
    for (int mt = 0; mt < 4; ++mt)
        a_off[mt] = (unsigned)((arow + mt * 16) * (LDS_PAD * 2) + acol * 2);
    unsigned b_off[2];
#pragma unroll
    for (int np = 0; np < 2; ++np) {
        int brow = wn * 32 + np * 16 + rr + (g & 1) * 8;
        b_off[np] = (unsigned)(brow * (LDS_PAD * 2) + acol * 2);
    }

    float acc[4][4][4];
#pragma unroll
    for (int i = 0; i < 4; ++i)
#pragma unroll
        for (int j = 0; j < 4; ++j)
#pragma unroll
            for (int k = 0; k < 4; ++k) acc[i][j][k] = 0.0f;

    const int NKC = NFEAT / BK;   // 256

    // ---- prologue: stage 0 ----
#pragma unroll
    for (int j = 0; j < 8; ++j)
        cp16(sbase + sdst[j], gsrc[j]);
    CP_COMMIT();

    for (int kc = 0; kc < NKC; ++kc) {
        CP_WAIT(0);            // buffer kc ready
        __syncthreads();       // everyone done with buffer kc-1 (== kc+1 slot)

        // issue load for chunk kc+1 into the freed slot (safe: post-barrier)
        if (kc + 1 < NKC) {
            const unsigned sb = sbase + ((kc + 1) & 1) * STAGEB;
            const size_t o = (size_t)(kc + 1) * BK;
#pragma unroll
            for (int j = 0; j < 8; ++j)
                cp16(sb + sdst[j], gsrc[j] + o);
            CP_COMMIT();
        }

        const unsigned buf = sbase + (kc & 1) * STAGEB;
#pragma unroll
        for (int kk = 0; kk < BK; kk += 16) {
            // pass 1+2 fragments: ahi, bhi, blo (peak frag liveness kept low;
            // alo loaded after ahi's last use so the regs can be reused)
            unsigned ahi[4][4], bhi[4][2], blo[4][2];
#pragma unroll
            for (int mt = 0; mt < 4; ++mt)
                ldsm4(ahi[mt][0], ahi[mt][1], ahi[mt][2], ahi[mt][3],
                      buf + OFF_AHI + a_off[mt] + kk * 2);
#pragma unroll
            for (int np = 0; np < 2; ++np) {
                unsigned f0, f1, f2, f3;
                ldsm4(f0, f1, f2, f3, buf + OFF_BHI + b_off[np] + kk * 2);
                bhi[2 * np][0] = f0; bhi[2 * np][1] = f2;
                bhi[2 * np + 1][0] = f1; bhi[2 * np + 1][1] = f3;
                ldsm4(f0, f1, f2, f3, buf + OFF_BLO + b_off[np] + kk * 2);
                blo[2 * np][0] = f0; blo[2 * np][1] = f2;
                blo[2 * np + 1][0] = f1; blo[2 * np + 1][1] = f3;
            }
#pragma unroll
            for (int mt = 0; mt < 4; ++mt)
#pragma unroll
                for (int nt = 0; nt < 4; ++nt)
                    mma_bf16(acc[mt][nt], ahi[mt], bhi[nt]);
#pragma unroll
            for (int mt = 0; mt < 4; ++mt)
#pragma unroll
                for (int nt = 0; nt < 4; ++nt)
                    mma_bf16(acc[mt][nt], ahi[mt], blo[nt]);

            // pass 3: alo (ahi dead now -> register reuse)
            unsigned alo[4][4];
#pragma unroll
            for (int mt = 0; mt < 4; ++mt)
                ldsm4(alo[mt][0], alo[mt][1], alo[mt][2], alo[mt][3],
                      buf + OFF_ALO + a_off[mt] + kk * 2);
#pragma unroll
            for (int mt = 0; mt < 4; ++mt)
#pragma unroll
                for (int nt = 0; nt < 4; ++nt)
                    mma_bf16(acc[mt][nt], alo[mt], bhi[nt]);
        }
    }

    // ---- writeback with strict-lower mask on diagonal tiles ----
    const bool diag = (bi == bj);
    const int qrow = lane >> 2;
    const int qcol = (lane & 3) * 2;
#pragma unroll
    for (int mt = 0; mt < 4; ++mt) {
#pragma unroll
        for (int nt = 0; nt < 4; ++nt) {
            int row = bi * 128 + wm * 64 + mt * 16 + qrow;
            int col = bj * 128 + wn * 32 + nt * 8 + qcol;
#pragma unroll
            for (int half = 0; half < 2; ++half) {
                int r = row + half * 8;
                float v0 = acc[mt][nt][half * 2 + 0];
                float v1 = acc[mt][nt][half * 2 + 1];
                if (diag) {
                    if (col + 0 >= r) v0 = 0.0f;
                    if (col + 1 >= r) v1 = 0.0f;
                }
                *(float2*)(Sh + (size_t)r * T_SEQ + col) = make_float2(v0, v1);
            }
        }
    }
}

// ============================================================================
// Kernel 4: out = S * V per head, reading only tiles kt <= bi (fp32 SIMT).
// ============================================================================
__global__ __launch_bounds__(256, 2) void gemm_out_kernel(const float* __restrict__ V,
                                                          float* __restrict__ O) {
    const int h  = blockIdx.z;
    const int bi = blockIdx.y;
    const int bj = blockIdx.x;
    const float* __restrict__ Sh = g_S + (size_t)h * T_SEQ * T_SEQ;
    float* __restrict__ Oh = O + (size_t)h * T_SEQ * DV;

    __shared__ float As[2][8][132];
    __shared__ float Bs[2][8][132];

    const int tid  = threadIdx.x;
    const int lrow = tid >> 1;
    const int c4   = (tid & 1) * 4;
    const float* ga = Sh + (size_t)(bi * 128 + lrow) * T_SEQ + c4;

    const int vrow = tid >> 5;
    const int vcol = (tid & 31) * 4;
    const float* gv = V + (size_t)vrow * DV + bj * 128 + vcol;

    const int tx = tid & 15, ty = tid >> 4;

    float acc[8][8];
#pragma unroll
    for (int i = 0; i < 8; ++i)
#pragma unroll
        for (int j = 0; j < 8; ++j) acc[i][j] = 0.0f;

    {
        float4 ra = *(const float4*)ga;
        float4 rv = *(const float4*)gv;
        As[0][c4 + 0][lrow] = ra.x; As[0][c4 + 1][lrow] = ra.y;
        As[0][c4 + 2][lrow] = ra.z; As[0][c4 + 3][lrow] = ra.w;
        *(float4*)&Bs[0][vrow][vcol] = rv;
    }
    __syncthreads();

    const int NK = (bi + 1) * 16;
    int buf = 0;
    for (int kc = 0; kc < NK; ++kc) {
        float4 na, nv;
        if (kc + 1 < NK) {
            na = *(const float4*)(ga + (size_t)(kc + 1) * 8);
            nv = *(const float4*)(gv + (size_t)(kc + 1) * 8 * DV);
        }
#pragma unroll
        for (int k = 0; k < 8; ++k) {
            float4 a0 = *(const float4*)&As[buf][k][ty * 8];
            float4 a1 = *(const float4*)&As[buf][k][ty * 8 + 4];
            float4 b0 = *(const float4*)&Bs[buf][k][tx * 8];
            float4 b1 = *(const float4*)&Bs[buf][k][tx * 8 + 4];
            float a[8] = {a0.x, a0.y, a0.z, a0.w, a1.x, a1.y, a1.z, a1.w};
            float b[8] = {b0.x, b0.y, b0.z, b0.w, b1.x, b1.y, b1.z, b1.w};
#pragma unroll
            for (int i = 0; i < 8; ++i)
#pragma unroll
                for (int j = 0; j < 8; ++j)
                    acc[i][j] = fmaf(a[i], b[j], acc[i][j]);
        }
        if (kc + 1 < NK) {
            int nb2 = buf ^ 1;
            As[nb2][c4 + 0][lrow] = na.x; As[nb2][c4 + 1][lrow] = na.y;
            As[nb2][c4 + 2][lrow] = na.z; As[nb2][c4 + 3][lrow] = na.w;
            *(float4*)&Bs[nb2][vrow][vcol] = nv;
        }
        __syncthreads();
        buf ^= 1;
    }

    const int row0 = bi * 128 + ty * 8;
    const int col0 = bj * 128 + tx * 8;
#pragma unroll
    for (int i = 0; i < 8; ++i) {
        float* dst = Oh + (size_t)(row0 + i) * DV + col0;
        *(float4*)(dst)     = make_float4(acc[i][0], acc[i][1], acc[i][2], acc[i][3]);
        *(float4*)(dst + 4) = make_float4(acc[i][4], acc[i][5], acc[i][6], acc[i][7]);
    }
}

// ============================================================================
extern "C" void kernel_launch(void* const* d_in, const int* in_sizes, int n_in,
                              void* d_out, int out_size) {
    const float* Q = (const float*)d_in[0];
    const float* V = (const float*)d_in[1];
    float* O = (float*)d_out;

    static bool attr_set = false;
    if (!attr_set) {
        cudaFuncSetAttribute(gemm_scores_kernel,
                             cudaFuncAttributeMaxDynamicSharedMemorySize, SMEM_BYTES);
        attr_set = true;
    }

    const int tab_elems  = T_SEQ * HALF_N;
    const int rope_pairs = NH * T_SEQ * HALF_N;

    freq_kernel<<<(HALF_N + 255) / 256, 256>>>();
    build_tab_kernel<<<(tab_elems + 255) / 256, 256>>>();
    rope_kernel<<<(rope_pairs + 255) / 256, 256>>>(Q);
    gemm_scores_kernel<<<dim3(136, NH), 256, SMEM_BYTES>>>();
    gemm_out_kernel<<<dim3(DV / 128, T_SEQ / 128, NH), 256>>>(V, O);
}

// round 14
// speedup vs baseline: 2.0276x; 1.8393x over previous
#include <cuda_runtime.h>
#include <cuda_bf16.h>
#include <cuda_fp16.h>
#include <math.h>
#include <stdint.h>

#define T_SEQ  2048
#define NFEAT  8192
#define NH     4
#define DV     256
#define HALF_N 4096   // NFEAT/2

// ---- device scratch (allocation-free rule: __device__ globals) ----
__device__ __half  g_Qh[(size_t)NH * T_SEQ * NFEAT];          // 134 MB (fp16, x64 scale)
__device__ float   g_S [(size_t)NH * T_SEQ * T_SEQ];          // 67 MB
__device__ float2  g_tab[(size_t)T_SEQ * HALF_N];             // 67 MB cos/sin
__device__ double  g_freq[HALF_N];

// ============================================================================
// helpers
// ============================================================================
__device__ __forceinline__ unsigned smem_u32(const void* p) {
    return (unsigned)__cvta_generic_to_shared(p);
}
__device__ __forceinline__ void cp16(unsigned dst, const void* src) {
    asm volatile("cp.async.cg.shared.global [%0], [%1], 16;" :: "r"(dst), "l"(src));
}
#define CP_COMMIT() asm volatile("cp.async.commit_group;" ::: "memory")
#define CP_WAIT(n)  asm volatile("cp.async.wait_group %0;" :: "n"(n) : "memory")

__device__ __forceinline__ void ldsm4(unsigned& r0, unsigned& r1, unsigned& r2, unsigned& r3,
                                      unsigned addr) {
    asm volatile("ldmatrix.sync.aligned.m8n8.x4.shared.b16 {%0,%1,%2,%3}, [%4];"
                 : "=r"(r0), "=r"(r1), "=r"(r2), "=r"(r3) : "r"(addr));
}
__device__ __forceinline__ void mma_f16(float* c, const unsigned* a, const unsigned* b) {
    asm volatile("mma.sync.aligned.m16n8k16.row.col.f32.f16.f16.f32 "
                 "{%0,%1,%2,%3}, {%4,%5,%6,%7}, {%8,%9}, {%0,%1,%2,%3};"
                 : "+f"(c[0]), "+f"(c[1]), "+f"(c[2]), "+f"(c[3])
                 : "r"(a[0]), "r"(a[1]), "r"(a[2]), "r"(a[3]), "r"(b[0]), "r"(b[1]));
}

// ============================================================================
// Kernel 0: per-pair frequency (fp64 exp2 hoisted)
// ============================================================================
__global__ void freq_kernel() {
    int p = blockIdx.x * 256 + threadIdx.x;
    if (p >= HALF_N) return;
    g_freq[p] = exp2(-(double)p * (1.0 / 256.0)) * (1.0 / (2.0 * M_PI));
}

// ============================================================================
// Kernel 1: cos/sin table. fp64 phase => exact mod-1; cospif/sinpif.
// ============================================================================
__global__ void build_tab_kernel() {
    int i = blockIdx.x * 256 + threadIdx.x;
    if (i >= T_SEQ * HALF_N) return;
    int t = i >> 12;
    int p = i & (HALF_N - 1);
    double phase = (double)t * g_freq[p];
    double fr    = phase - floor(phase);
    float  x     = (float)(2.0 * fr);
    g_tab[i] = make_float2(cospif(x), sinpif(x));
}

// ============================================================================
// Kernel 2: RoPE -> fp16 scaled by 64 (keeps everything in fp16 normal range)
// ============================================================================
__global__ void rope_kernel(const float* __restrict__ Q) {
    size_t i = (size_t)blockIdx.x * 256 + threadIdx.x;
    if (i >= (size_t)NH * T_SEQ * HALF_N) return;
    size_t r = i & ((size_t)T_SEQ * HALF_N - 1);
    float2 q  = ((const float2*)Q)[i];
    float2 cs = g_tab[r];
    float ox = (q.x * cs.x - q.y * cs.y) * 64.0f;
    float oy = (q.y * cs.x + q.x * cs.y) * 64.0f;
    __half2 hv; hv.x = __float2half_rn(ox); hv.y = __float2half_rn(oy);
    ((__half2*)g_Qh)[i] = hv;
}

// ============================================================================
// Kernel 3: S = tril(QR*QR^T, k=-1)/4096, single-pass fp16 HMMA.
// 256 threads (8 warps, 2m x 4n of 64x32), 128x128 tile, BK=32,
// cp.async double-buffer, one barrier per chunk, 2 CTAs/SM.
// ============================================================================
#define BK        32
#define LDS_PAD   40
#define ARRB      (128 * LDS_PAD * 2)      // 10240
#define STAGEB    (2 * ARRB)               // 20480 (A, B)
#define SMEM_BYTES (2 * STAGEB)            // 40960

#define OFF_A 0
#define OFF_B ARRB

__global__ __launch_bounds__(256, 2) void gemm_scores_kernel() {
    extern __shared__ __align__(128) char smem[];
    const unsigned sbase = smem_u32(smem);

    const int h = blockIdx.y;
    const __half* __restrict__ Qh = g_Qh + (size_t)h * T_SEQ * NFEAT;
    float* __restrict__ Sh = g_S + (size_t)h * T_SEQ * T_SEQ;

    // lower-triangular tile decode
    int lt = blockIdx.x;
    int bi = (int)((sqrtf(8.0f * (float)lt + 1.0f) - 1.0f) * 0.5f);
    while ((bi + 1) * (bi + 2) / 2 <= lt) ++bi;
    while (bi * (bi + 1) / 2 > lt)        --bi;
    const int bj = lt - bi * (bi + 1) / 2;

    const int tid  = threadIdx.x;
    const int lane = tid & 31;
    const int wid  = tid >> 5;
    const int wm   = wid >> 2;   // 0..1
    const int wn   = wid & 3;    // 0..3

    // ---- global-load mapping: 4 x 16B cp.async per thread per stage ----
    const __half* srcA[2];
    srcA[0] = Qh + (size_t)(bi * 128) * NFEAT;
    srcA[1] = Qh + (size_t)(bj * 128) * NFEAT;

    unsigned sdst[4];
    const __half* gsrc[4];
#pragma unroll
    for (int j = 0; j < 4; ++j) {
        int idx = j * 256 + tid;        // 0..1023
        int arr = idx >> 9;             // 0..1
        int rem = idx & 511;
        int row = rem >> 2;
        int c16 = rem & 3;
        sdst[j] = (unsigned)(arr * ARRB + row * (LDS_PAD * 2) + c16 * 16);
        gsrc[j] = srcA[arr] + (size_t)row * NFEAT + c16 * 8;
    }

    // ---- ldmatrix lane offsets (64x32 per warp) ----
    const int g  = lane >> 3;
    const int rr = lane & 7;
    const int arow = wm * 64 + rr + (g & 1) * 8;
    const int acol = (g >> 1) * 8;
    unsigned a_off[4];
#pragma unroll
    for (int mt = 0; mt < 4; ++mt)
        a_off[mt] = (unsigned)((arow + mt * 16) * (LDS_PAD * 2) + acol * 2);
    unsigned b_off[2];
#pragma unroll
    for (int np = 0; np < 2; ++np) {
        int brow = wn * 32 + np * 16 + rr + (g & 1) * 8;
        b_off[np] = (unsigned)(brow * (LDS_PAD * 2) + acol * 2);
    }

    float acc[4][4][4];
#pragma unroll
    for (int i = 0; i < 4; ++i)
#pragma unroll
        for (int j = 0; j < 4; ++j)
#pragma unroll
            for (int k = 0; k < 4; ++k) acc[i][j][k] = 0.0f;

    const int NKC = NFEAT / BK;   // 256

    // ---- prologue: stage 0 ----
#pragma unroll
    for (int j = 0; j < 4; ++j)
        cp16(sbase + sdst[j], gsrc[j]);
    CP_COMMIT();

    for (int kc = 0; kc < NKC; ++kc) {
        CP_WAIT(0);
        __syncthreads();

        if (kc + 1 < NKC) {
            const unsigned sb = sbase + ((kc + 1) & 1) * STAGEB;
            const size_t o = (size_t)(kc + 1) * BK;
#pragma unroll
            for (int j = 0; j < 4; ++j)
                cp16(sb + sdst[j], gsrc[j] + o);
            CP_COMMIT();
        }

        const unsigned buf = sbase + (kc & 1) * STAGEB;
#pragma unroll
        for (int kk = 0; kk < BK; kk += 16) {
            unsigned a[4][4], b[4][2];
#pragma unroll
            for (int mt = 0; mt < 4; ++mt)
                ldsm4(a[mt][0], a[mt][1], a[mt][2], a[mt][3],
                      buf + OFF_A + a_off[mt] + kk * 2);
#pragma unroll
            for (int np = 0; np < 2; ++np) {
                unsigned f0, f1, f2, f3;
                ldsm4(f0, f1, f2, f3, buf + OFF_B + b_off[np] + kk * 2);
                b[2 * np][0] = f0; b[2 * np][1] = f2;
                b[2 * np + 1][0] = f1; b[2 * np + 1][1] = f3;
            }
#pragma unroll
            for (int mt = 0; mt < 4; ++mt)
#pragma unroll
                for (int nt = 0; nt < 4; ++nt)
                    mma_f16(acc[mt][nt], a[mt], b[nt]);
        }
    }

    // ---- writeback: scale by 1/4096 (undo 64x input scaling), mask diag ----
    const bool diag = (bi == bj);
    const float inv = 1.0f / 4096.0f;
    const int qrow = lane >> 2;
    const int qcol = (lane & 3) * 2;
#pragma unroll
    for (int mt = 0; mt < 4; ++mt) {
#pragma unroll
        for (int nt = 0; nt < 4; ++nt) {
            int row = bi * 128 + wm * 64 + mt * 16 + qrow;
            int col = bj * 128 + wn * 32 + nt * 8 + qcol;
#pragma unroll
            for (int half = 0; half < 2; ++half) {
                int r = row + half * 8;
                float v0 = acc[mt][nt][half * 2 + 0] * inv;
                float v1 = acc[mt][nt][half * 2 + 1] * inv;
                if (diag) {
                    if (col + 0 >= r) v0 = 0.0f;
                    if (col + 1 >= r) v1 = 0.0f;
                }
                *(float2*)(Sh + (size_t)r * T_SEQ + col) = make_float2(v0, v1);
            }
        }
    }
}

// ============================================================================
// Kernel 4: out = S * V per head, reading only tiles kt <= bi (fp32 SIMT).
// ============================================================================
__global__ __launch_bounds__(256, 2) void gemm_out_kernel(const float* __restrict__ V,
                                                          float* __restrict__ O) {
    const int h  = blockIdx.z;
    const int bi = blockIdx.y;
    const int bj = blockIdx.x;
    const float* __restrict__ Sh = g_S + (size_t)h * T_SEQ * T_SEQ;
    float* __restrict__ Oh = O + (size_t)h * T_SEQ * DV;

    __shared__ float As[2][8][132];
    __shared__ float Bs[2][8][132];

    const int tid  = threadIdx.x;
    const int lrow = tid >> 1;
    const int c4   = (tid & 1) * 4;
    const float* ga = Sh + (size_t)(bi * 128 + lrow) * T_SEQ + c4;

    const int vrow = tid >> 5;
    const int vcol = (tid & 31) * 4;
    const float* gv = V + (size_t)vrow * DV + bj * 128 + vcol;

    const int tx = tid & 15, ty = tid >> 4;

    float acc[8][8];
#pragma unroll
    for (int i = 0; i < 8; ++i)
#pragma unroll
        for (int j = 0; j < 8; ++j) acc[i][j] = 0.0f;

    {
        float4 ra = *(const float4*)ga;
        float4 rv = *(const float4*)gv;
        As[0][c4 + 0][lrow] = ra.x; As[0][c4 + 1][lrow] = ra.y;
        As[0][c4 + 2][lrow] = ra.z; As[0][c4 + 3][lrow] = ra.w;
        *(float4*)&Bs[0][vrow][vcol] = rv;
    }
    __syncthreads();

    const int NK = (bi + 1) * 16;
    int buf = 0;
    for (int kc = 0; kc < NK; ++kc) {
        float4 na, nv;
        if (kc + 1 < NK) {
            na = *(const float4*)(ga + (size_t)(kc + 1) * 8);
            nv = *(const float4*)(gv + (size_t)(kc + 1) * 8 * DV);
        }
#pragma unroll
        for (int k = 0; k < 8; ++k) {
            float4 a0 = *(const float4*)&As[buf][k][ty * 8];
            float4 a1 = *(const float4*)&As[buf][k][ty * 8 + 4];
            float4 b0 = *(const float4*)&Bs[buf][k][tx * 8];
            float4 b1 = *(const float4*)&Bs[buf][k][tx * 8 + 4];
            float a[8] = {a0.x, a0.y, a0.z, a0.w, a1.x, a1.y, a1.z, a1.w};
            float b[8] = {b0.x, b0.y, b0.z, b0.w, b1.x, b1.y, b1.z, b1.w};
#pragma unroll
            for (int i = 0; i < 8; ++i)
#pragma unroll
                for (int j = 0; j < 8; ++j)
                    acc[i][j] = fmaf(a[i], b[j], acc[i][j]);
        }
        if (kc + 1 < NK) {
            int nb2 = buf ^ 1;
            As[nb2][c4 + 0][lrow] = na.x; As[nb2][c4 + 1][lrow] = na.y;
            As[nb2][c4 + 2][lrow] = na.z; As[nb2][c4 + 3][lrow] = na.w;
            *(float4*)&Bs[nb2][vrow][vcol] = nv;
        }
        __syncthreads();
        buf ^= 1;
    }

    const int row0 = bi * 128 + ty * 8;
    const int col0 = bj * 128 + tx * 8;
#pragma unroll
    for (int i = 0; i < 8; ++i) {
        float* dst = Oh + (size_t)(row0 + i) * DV + col0;
        *(float4*)(dst)     = make_float4(acc[i][0], acc[i][1], acc[i][2], acc[i][3]);
        *(float4*)(dst + 4) = make_float4(acc[i][4], acc[i][5], acc[i][6], acc[i][7]);
    }
}

// ============================================================================
extern "C" void kernel_launch(void* const* d_in, const int* in_sizes, int n_in,
                              void* d_out, int out_size) {
    const float* Q = (const float*)d_in[0];
    const float* V = (const float*)d_in[1];
    float* O = (float*)d_out;

    static bool attr_set = false;
    if (!attr_set) {
        cudaFuncSetAttribute(gemm_scores_kernel,
                             cudaFuncAttributeMaxDynamicSharedMemorySize, SMEM_BYTES);
        attr_set = true;
    }

    const int tab_elems  = T_SEQ * HALF_N;
    const int rope_pairs = NH * T_SEQ * HALF_N;

    freq_kernel<<<(HALF_N + 255) / 256, 256>>>();
    build_tab_kernel<<<(tab_elems + 255) / 256, 256>>>();
    rope_kernel<<<(rope_pairs + 255) / 256, 256>>>(Q);
    gemm_scores_kernel<<<dim3(136, NH), 256, SMEM_BYTES>>>();
    gemm_out_kernel<<<dim3(DV / 128, T_SEQ / 128, NH), 256>>>(V, O);
}

// round 15
// speedup vs baseline: 2.5504x; 1.2579x over previous
#include <cuda_runtime.h>
#include <cuda_bf16.h>
#include <cuda_fp16.h>
#include <math.h>
#include <stdint.h>

#define T_SEQ  2048
#define NFEAT  8192
#define NH     4
#define DV     256
#define HALF_N 4096   // NFEAT/2

// ---- device scratch (allocation-free rule: __device__ globals) ----
__device__ __half  g_Qh[(size_t)NH * T_SEQ * NFEAT];          // 134 MB (fp16, x64 scale)
__device__ __half  g_S [(size_t)NH * T_SEQ * T_SEQ];          // 34 MB (fp16 scores)
__device__ __half  g_Vt[(size_t)DV * T_SEQ];                  // 1 MB  (V^T fp16)
__device__ float2  g_tab[(size_t)T_SEQ * HALF_N];             // 67 MB cos/sin
__device__ double  g_freq[HALF_N];

// ============================================================================
// helpers
// ============================================================================
__device__ __forceinline__ unsigned smem_u32(const void* p) {
    return (unsigned)__cvta_generic_to_shared(p);
}
__device__ __forceinline__ void cp16(unsigned dst, const void* src) {
    asm volatile("cp.async.cg.shared.global [%0], [%1], 16;" :: "r"(dst), "l"(src));
}
#define CP_COMMIT() asm volatile("cp.async.commit_group;" ::: "memory")
#define CP_WAIT(n)  asm volatile("cp.async.wait_group %0;" :: "n"(n) : "memory")

__device__ __forceinline__ void ldsm4(unsigned& r0, unsigned& r1, unsigned& r2, unsigned& r3,
                                      unsigned addr) {
    asm volatile("ldmatrix.sync.aligned.m8n8.x4.shared.b16 {%0,%1,%2,%3}, [%4];"
                 : "=r"(r0), "=r"(r1), "=r"(r2), "=r"(r3) : "r"(addr));
}
__device__ __forceinline__ void mma_f16(float* c, const unsigned* a, const unsigned* b) {
    asm volatile("mma.sync.aligned.m16n8k16.row.col.f32.f16.f16.f32 "
                 "{%0,%1,%2,%3}, {%4,%5,%6,%7}, {%8,%9}, {%0,%1,%2,%3};"
                 : "+f"(c[0]), "+f"(c[1]), "+f"(c[2]), "+f"(c[3])
                 : "r"(a[0]), "r"(a[1]), "r"(a[2]), "r"(a[3]), "r"(b[0]), "r"(b[1]));
}

// ============================================================================
// Kernel 0: per-pair frequency (fp64 exp2 hoisted)
// ============================================================================
__global__ void freq_kernel() {
    int p = blockIdx.x * 256 + threadIdx.x;
    if (p >= HALF_N) return;
    g_freq[p] = exp2(-(double)p * (1.0 / 256.0)) * (1.0 / (2.0 * M_PI));
}

// ============================================================================
// Kernel 1: cos/sin table. fp64 phase => exact mod-1; cospif/sinpif.
// ============================================================================
__global__ void build_tab_kernel() {
    int i = blockIdx.x * 256 + threadIdx.x;
    if (i >= T_SEQ * HALF_N) return;
    int t = i >> 12;
    int p = i & (HALF_N - 1);
    double phase = (double)t * g_freq[p];
    double fr    = phase - floor(phase);
    float  x     = (float)(2.0 * fr);
    g_tab[i] = make_float2(cospif(x), sinpif(x));
}

// ============================================================================
// Kernel 2: RoPE -> fp16 scaled by 64
// ============================================================================
__global__ void rope_kernel(const float* __restrict__ Q) {
    size_t i = (size_t)blockIdx.x * 256 + threadIdx.x;
    if (i >= (size_t)NH * T_SEQ * HALF_N) return;
    size_t r = i & ((size_t)T_SEQ * HALF_N - 1);
    float2 q  = ((const float2*)Q)[i];
    float2 cs = g_tab[r];
    float ox = (q.x * cs.x - q.y * cs.y) * 64.0f;
    float oy = (q.y * cs.x + q.x * cs.y) * 64.0f;
    __half2 hv; hv.x = __float2half_rn(ox); hv.y = __float2half_rn(oy);
    ((__half2*)g_Qh)[i] = hv;
}

// ============================================================================
// Kernel 2b: V (2048x256 f32) -> Vt (256x2048 fp16), smem tile transpose
// ============================================================================
__global__ void vt_kernel(const float* __restrict__ V) {
    __shared__ float tile[32][33];
    const int t0 = blockIdx.x * 32;     // seq block
    const int d0 = blockIdx.y * 32;     // dim block
    const int tx = threadIdx.x & 31;
    const int ty = threadIdx.x >> 5;    // 0..7
#pragma unroll
    for (int i = 0; i < 32; i += 8)
        tile[ty + i][tx] = V[(size_t)(t0 + ty + i) * DV + d0 + tx];
    __syncthreads();
#pragma unroll
    for (int i = 0; i < 32; i += 8)
        g_Vt[(size_t)(d0 + ty + i) * T_SEQ + t0 + tx] = __float2half_rn(tile[tx][ty + i]);
}

// ============================================================================
// Kernel 3: S = tril(QR*QR^T, k=-1)/4096 in fp16, single-pass fp16 HMMA.
// 256 threads (8 warps, 2m x 4n of 64x32), 128x128 tile, BK=32,
// cp.async double-buffer, one barrier per chunk, 2 CTAs/SM.
// ============================================================================
#define BK        32
#define LDS_PAD   40
#define ARRB      (128 * LDS_PAD * 2)      // 10240
#define STAGEB    (2 * ARRB)               // 20480 (A, B)
#define SMEM_BYTES (2 * STAGEB)            // 40960

#define OFF_A 0
#define OFF_B ARRB

__global__ __launch_bounds__(256, 2) void gemm_scores_kernel() {
    extern __shared__ __align__(128) char smem[];
    const unsigned sbase = smem_u32(smem);

    const int h = blockIdx.y;
    const __half* __restrict__ Qh = g_Qh + (size_t)h * T_SEQ * NFEAT;
    __half* __restrict__ Sh = g_S + (size_t)h * T_SEQ * T_SEQ;

    int lt = blockIdx.x;
    int bi = (int)((sqrtf(8.0f * (float)lt + 1.0f) - 1.0f) * 0.5f);
    while ((bi + 1) * (bi + 2) / 2 <= lt) ++bi;
    while (bi * (bi + 1) / 2 > lt)        --bi;
    const int bj = lt - bi * (bi + 1) / 2;

    const int tid  = threadIdx.x;
    const int lane = tid & 31;
    const int wid  = tid >> 5;
    const int wm   = wid >> 2;
    const int wn   = wid & 3;

    const __half* srcA[2];
    srcA[0] = Qh + (size_t)(bi * 128) * NFEAT;
    srcA[1] = Qh + (size_t)(bj * 128) * NFEAT;

    unsigned sdst[4];
    const __half* gsrc[4];
#pragma unroll
    for (int j = 0; j < 4; ++j) {
        int idx = j * 256 + tid;
        int arr = idx >> 9;
        int rem = idx & 511;
        int row = rem >> 2;
        int c16 = rem & 3;
        sdst[j] = (unsigned)(arr * ARRB + row * (LDS_PAD * 2) + c16 * 16);
        gsrc[j] = srcA[arr] + (size_t)row * NFEAT + c16 * 8;
    }

    const int g  = lane >> 3;
    const int rr = lane & 7;
    const int arow = wm * 64 + rr + (g & 1) * 8;
    const int acol = (g >> 1) * 8;
    unsigned a_off[4];
#pragma unroll
    for (int mt = 0; mt < 4; ++mt)
        a_off[mt] = (unsigned)((arow + mt * 16) * (LDS_PAD * 2) + acol * 2);
    unsigned b_off[2];
#pragma unroll
    for (int np = 0; np < 2; ++np) {
        int brow = wn * 32 + np * 16 + rr + (g & 1) * 8;
        b_off[np] = (unsigned)(brow * (LDS_PAD * 2) + acol * 2);
    }

    float acc[4][4][4];
#pragma unroll
    for (int i = 0; i < 4; ++i)
#pragma unroll
        for (int j = 0; j < 4; ++j)
#pragma unroll
            for (int k = 0; k < 4; ++k) acc[i][j][k] = 0.0f;

    const int NKC = NFEAT / BK;   // 256

#pragma unroll
    for (int j = 0; j < 4; ++j)
        cp16(sbase + sdst[j], gsrc[j]);
    CP_COMMIT();

    for (int kc = 0; kc < NKC; ++kc) {
        CP_WAIT(0);
        __syncthreads();

        if (kc + 1 < NKC) {
            const unsigned sb = sbase + ((kc + 1) & 1) * STAGEB;
            const size_t o = (size_t)(kc + 1) * BK;
#pragma unroll
            for (int j = 0; j < 4; ++j)
                cp16(sb + sdst[j], gsrc[j] + o);
            CP_COMMIT();
        }

        const unsigned buf = sbase + (kc & 1) * STAGEB;
#pragma unroll
        for (int kk = 0; kk < BK; kk += 16) {
            unsigned a[4][4], b[4][2];
#pragma unroll
            for (int mt = 0; mt < 4; ++mt)
                ldsm4(a[mt][0], a[mt][1], a[mt][2], a[mt][3],
                      buf + OFF_A + a_off[mt] + kk * 2);
#pragma unroll
            for (int np = 0; np < 2; ++np) {
                unsigned f0, f1, f2, f3;
                ldsm4(f0, f1, f2, f3, buf + OFF_B + b_off[np] + kk * 2);
                b[2 * np][0] = f0; b[2 * np][1] = f2;
                b[2 * np + 1][0] = f1; b[2 * np + 1][1] = f3;
            }
#pragma unroll
            for (int mt = 0; mt < 4; ++mt)
#pragma unroll
                for (int nt = 0; nt < 4; ++nt)
                    mma_f16(acc[mt][nt], a[mt], b[nt]);
        }
    }

    // ---- writeback: scale by 1/4096, mask diag, store fp16 ----
    const bool diag = (bi == bj);
    const float inv = 1.0f / 4096.0f;
    const int qrow = lane >> 2;
    const int qcol = (lane & 3) * 2;
#pragma unroll
    for (int mt = 0; mt < 4; ++mt) {
#pragma unroll
        for (int nt = 0; nt < 4; ++nt) {
            int row = bi * 128 + wm * 64 + mt * 16 + qrow;
            int col = bj * 128 + wn * 32 + nt * 8 + qcol;
#pragma unroll
            for (int half = 0; half < 2; ++half) {
                int r = row + half * 8;
                float v0 = acc[mt][nt][half * 2 + 0] * inv;
                float v1 = acc[mt][nt][half * 2 + 1] * inv;
                if (diag) {
                    if (col + 0 >= r) v0 = 0.0f;
                    if (col + 1 >= r) v1 = 0.0f;
                }
                __half2 hv; hv.x = __float2half_rn(v0); hv.y = __float2half_rn(v1);
                *(__half2*)(Sh + (size_t)r * T_SEQ + col) = hv;
            }
        }
    }
}

// ============================================================================
// Kernel 4: O = S * V via fp16 HMMA.  A = S (k-contig fp16), B = Vt (k-contig
// fp16) -> identical fragment layout to scores.  K = (bi+1)*128.
// Grid (DV/128, T_SEQ/128, NH).
// ============================================================================
__global__ __launch_bounds__(256, 2) void gemm_out_kernel(float* __restrict__ O) {
    extern __shared__ __align__(128) char smem[];
    const unsigned sbase = smem_u32(smem);

    const int h  = blockIdx.z;
    const int bi = blockIdx.y;   // row tile 0..15
    const int bj = blockIdx.x;   // col tile 0..1
    const __half* __restrict__ Sh = g_S + (size_t)h * T_SEQ * T_SEQ;
    float* __restrict__ Oh = O + (size_t)h * T_SEQ * DV;

    const int tid  = threadIdx.x;
    const int lane = tid & 31;
    const int wid  = tid >> 5;
    const int wm   = wid >> 2;
    const int wn   = wid & 3;

    const __half* srcA[2];
    srcA[0] = Sh + (size_t)(bi * 128) * T_SEQ;
    srcA[1] = g_Vt + (size_t)(bj * 128) * T_SEQ;

    unsigned sdst[4];
    const __half* gsrc[4];
#pragma unroll
    for (int j = 0; j < 4; ++j) {
        int idx = j * 256 + tid;
        int arr = idx >> 9;
        int rem = idx & 511;
        int row = rem >> 2;
        int c16 = rem & 3;
        sdst[j] = (unsigned)(arr * ARRB + row * (LDS_PAD * 2) + c16 * 16);
        gsrc[j] = srcA[arr] + (size_t)row * T_SEQ + c16 * 8;
    }

    const int g  = lane >> 3;
    const int rr = lane & 7;
    const int arow = wm * 64 + rr + (g & 1) * 8;
    const int acol = (g >> 1) * 8;
    unsigned a_off[4];
#pragma unroll
    for (int mt = 0; mt < 4; ++mt)
        a_off[mt] = (unsigned)((arow + mt * 16) * (LDS_PAD * 2) + acol * 2);
    unsigned b_off[2];
#pragma unroll
    for (int np = 0; np < 2; ++np) {
        int brow = wn * 32 + np * 16 + rr + (g & 1) * 8;
        b_off[np] = (unsigned)(brow * (LDS_PAD * 2) + acol * 2);
    }

    float acc[4][4][4];
#pragma unroll
    for (int i = 0; i < 4; ++i)
#pragma unroll
        for (int j = 0; j < 4; ++j)
#pragma unroll
            for (int k = 0; k < 4; ++k) acc[i][j][k] = 0.0f;

    const int NKC = (bi + 1) * (128 / BK);   // (bi+1)*4 chunks

#pragma unroll
    for (int j = 0; j < 4; ++j)
        cp16(sbase + sdst[j], gsrc[j]);
    CP_COMMIT();

    for (int kc = 0; kc < NKC; ++kc) {
        CP_WAIT(0);
        __syncthreads();

        if (kc + 1 < NKC) {
            const unsigned sb = sbase + ((kc + 1) & 1) * STAGEB;
            const size_t o = (size_t)(kc + 1) * BK;
#pragma unroll
            for (int j = 0; j < 4; ++j)
                cp16(sb + sdst[j], gsrc[j] + o);
            CP_COMMIT();
        }

        const unsigned buf = sbase + (kc & 1) * STAGEB;
#pragma unroll
        for (int kk = 0; kk < BK; kk += 16) {
            unsigned a[4][4], b[4][2];
#pragma unroll
            for (int mt = 0; mt < 4; ++mt)
                ldsm4(a[mt][0], a[mt][1], a[mt][2], a[mt][3],
                      buf + OFF_A + a_off[mt] + kk * 2);
#pragma unroll
            for (int np = 0; np < 2; ++np) {
                unsigned f0, f1, f2, f3;
                ldsm4(f0, f1, f2, f3, buf + OFF_B + b_off[np] + kk * 2);
                b[2 * np][0] = f0; b[2 * np][1] = f2;
                b[2 * np + 1][0] = f1; b[2 * np + 1][1] = f3;
            }
#pragma unroll
            for (int mt = 0; mt < 4; ++mt)
#pragma unroll
                for (int nt = 0; nt < 4; ++nt)
                    mma_f16(acc[mt][nt], a[mt], b[nt]);
        }
    }

    // ---- writeback fp32 ----
    const int qrow = lane >> 2;
    const int qcol = (lane & 3) * 2;
#pragma unroll
    for (int mt = 0; mt < 4; ++mt) {
#pragma unroll
        for (int nt = 0; nt < 4; ++nt) {
            int row = bi * 128 + wm * 64 + mt * 16 + qrow;
            int col = bj * 128 + wn * 32 + nt * 8 + qcol;
#pragma unroll
            for (int half = 0; half < 2; ++half) {
                int r = row + half * 8;
                *(float2*)(Oh + (size_t)r * DV + col) =
                    make_float2(acc[mt][nt][half * 2 + 0], acc[mt][nt][half * 2 + 1]);
            }
        }
    }
}

// ============================================================================
extern "C" void kernel_launch(void* const* d_in, const int* in_sizes, int n_in,
                              void* d_out, int out_size) {
    const float* Q = (const float*)d_in[0];
    const float* V = (const float*)d_in[1];
    float* O = (float*)d_out;

    static bool attr_set = false;
    if (!attr_set) {
        cudaFuncSetAttribute(gemm_scores_kernel,
                             cudaFuncAttributeMaxDynamicSharedMemorySize, SMEM_BYTES);
        cudaFuncSetAttribute(gemm_out_kernel,
                             cudaFuncAttributeMaxDynamicSharedMemorySize, SMEM_BYTES);
        attr_set = true;
    }

    const int tab_elems  = T_SEQ * HALF_N;
    const int rope_pairs = NH * T_SEQ * HALF_N;

    freq_kernel<<<(HALF_N + 255) / 256, 256>>>();
    build_tab_kernel<<<(tab_elems + 255) / 256, 256>>>();
    rope_kernel<<<(rope_pairs + 255) / 256, 256>>>(Q);
    vt_kernel<<<dim3(T_SEQ / 32, DV / 32), 256>>>(V);
    gemm_scores_kernel<<<dim3(136, NH), 256, SMEM_BYTES>>>();
    gemm_out_kernel<<<dim3(DV / 128, T_SEQ / 128, NH), 256, SMEM_BYTES>>>(O);
}

// round 17
// speedup vs baseline: 3.0383x; 1.1913x over previous
#include <cuda_runtime.h>
#include <cuda_bf16.h>
#include <cuda_fp16.h>
#include <math.h>
#include <stdint.h>

#define T_SEQ  2048
#define NFEAT  8192
#define NH     4
#define DV     256
#define HALF_N 4096   // NFEAT/2

// ---- device scratch (allocation-free rule: __device__ globals) ----
__device__ __half  g_Qh[(size_t)NH * T_SEQ * NFEAT];          // 134 MB (fp16, x64 scale)
__device__ __half  g_S [(size_t)NH * T_SEQ * T_SEQ];          // 34 MB (fp16 scores)
__device__ __half  g_Vt[(size_t)DV * T_SEQ];                  // 1 MB  (V^T fp16)
__device__ float2  g_tab[(size_t)T_SEQ * HALF_N];             // 67 MB cos/sin
__device__ double  g_freq[HALF_N];

// ============================================================================
// helpers
// ============================================================================
__device__ __forceinline__ unsigned smem_u32(const void* p) {
    return (unsigned)__cvta_generic_to_shared(p);
}
__device__ __forceinline__ void cp16(unsigned dst, const void* src) {
    asm volatile("cp.async.cg.shared.global [%0], [%1], 16;" :: "r"(dst), "l"(src));
}
#define CP_COMMIT() asm volatile("cp.async.commit_group;" ::: "memory")
#define CP_WAIT(n)  asm volatile("cp.async.wait_group %0;" :: "n"(n) : "memory")

__device__ __forceinline__ void ldsm4(unsigned& r0, unsigned& r1, unsigned& r2, unsigned& r3,
                                      unsigned addr) {
    asm volatile("ldmatrix.sync.aligned.m8n8.x4.shared.b16 {%0,%1,%2,%3}, [%4];"
                 : "=r"(r0), "=r"(r1), "=r"(r2), "=r"(r3) : "r"(addr));
}
__device__ __forceinline__ void mma_f16(float* c, const unsigned* a, const unsigned* b) {
    asm volatile("mma.sync.aligned.m16n8k16.row.col.f32.f16.f16.f32 "
                 "{%0,%1,%2,%3}, {%4,%5,%6,%7}, {%8,%9}, {%0,%1,%2,%3};"
                 : "+f"(c[0]), "+f"(c[1]), "+f"(c[2]), "+f"(c[3])
                 : "r"(a[0]), "r"(a[1]), "r"(a[2]), "r"(a[3]), "r"(b[0]), "r"(b[1]));
}

// ============================================================================
// Kernel 0: per-pair frequency (fp64 exp2 hoisted)
// ============================================================================
__global__ void freq_kernel() {
    int p = blockIdx.x * 256 + threadIdx.x;
    if (p >= HALF_N) return;
    g_freq[p] = exp2(-(double)p * (1.0 / 256.0)) * (1.0 / (2.0 * M_PI));
}

// ============================================================================
// Kernel 1: cos/sin table. fp64 phase => exact mod-1.  Trig via MUFU:
// x = (fr-0.5)*2pi in [-pi,pi];  cos(2pi*fr) = -cos(x), sin(2pi*fr) = -sin(x).
// MUFU abs err ~4e-7 -- negligible vs fp16 rounding (5e-4).
// ============================================================================
__global__ void build_tab_kernel() {
    int i = blockIdx.x * 256 + threadIdx.x;
    if (i >= T_SEQ * HALF_N) return;
    int t = i >> 12;
    int p = i & (HALF_N - 1);
    double phase = (double)t * g_freq[p];
    float  fr    = (float)(phase - floor(phase));
    float  x     = (fr - 0.5f) * 6.283185307179586f;
    float  s, c;
    __sincosf(x, &s, &c);
    g_tab[i] = make_float2(-c, -s);
}

// ============================================================================
// Kernel 2: RoPE -> fp16 scaled by 64.  One thread = one (t, pair) position,
// all 4 heads (amortizes the cos/sin table read 4x).
// ============================================================================
__global__ void rope_kernel(const float* __restrict__ Q) {
    size_t i = (size_t)blockIdx.x * 256 + threadIdx.x;   // pair index in head 0
    if (i >= (size_t)T_SEQ * HALF_N) return;
    float2 cs = g_tab[i];
#pragma unroll
    for (int h = 0; h < NH; ++h) {
        size_t idx = i + (size_t)h * (T_SEQ * (size_t)HALF_N);
        float2 q  = ((const float2*)Q)[idx];
        float ox = (q.x * cs.x - q.y * cs.y) * 64.0f;
        float oy = (q.y * cs.x + q.x * cs.y) * 64.0f;
        __half2 hv; hv.x = __float2half_rn(ox); hv.y = __float2half_rn(oy);
        ((__half2*)g_Qh)[idx] = hv;
    }
}

// ============================================================================
// Kernel 2b: V (2048x256 f32) -> Vt (256x2048 fp16), smem tile transpose
// ============================================================================
__global__ void vt_kernel(const float* __restrict__ V) {
    __shared__ float tile[32][33];
    const int t0 = blockIdx.x * 32;
    const int d0 = blockIdx.y * 32;
    const int tx = threadIdx.x & 31;
    const int ty = threadIdx.x >> 5;
#pragma unroll
    for (int i = 0; i < 32; i += 8)
        tile[ty + i][tx] = V[(size_t)(t0 + ty + i) * DV + d0 + tx];
    __syncthreads();
#pragma unroll
    for (int i = 0; i < 32; i += 8)
        g_Vt[(size_t)(d0 + ty + i) * T_SEQ + t0 + tx] = __float2half_rn(tile[tx][ty + i]);
}

// ============================================================================
// Kernel 3: S = tril(QR*QR^T, k=-1)/4096 in fp16, single-pass fp16 HMMA.
// 256 threads (8 warps, 2m x 4n of 64x32), 128x128 tile, BK=64,
// cp.async double-buffer, one barrier per chunk, 2 CTAs/SM.
// ============================================================================
#define BKS       64
#define PAD_S     72                        // halfs per row (64 + 8 pad)
#define ARR_S     (128 * PAD_S * 2)         // 18432 B per array
#define STAGE_S   (2 * ARR_S)               // 36864 (A, B)
#define SMEM_S    (2 * STAGE_S)             // 73728

__global__ __launch_bounds__(256, 2) void gemm_scores_kernel() {
    extern __shared__ __align__(128) char smem[];
    const unsigned sbase = smem_u32(smem);

    const int h = blockIdx.y;
    const __half* __restrict__ Qh = g_Qh + (size_t)h * T_SEQ * NFEAT;
    __half* __restrict__ Sh = g_S + (size_t)h * T_SEQ * T_SEQ;

    int lt = blockIdx.x;
    int bi = (int)((sqrtf(8.0f * (float)lt + 1.0f) - 1.0f) * 0.5f);
    while ((bi + 1) * (bi + 2) / 2 <= lt) ++bi;
    while (bi * (bi + 1) / 2 > lt)        --bi;
    const int bj = lt - bi * (bi + 1) / 2;

    const int tid  = threadIdx.x;
    const int lane = tid & 31;
    const int wid  = tid >> 5;
    const int wm   = wid >> 2;
    const int wn   = wid & 3;

    const __half* srcA[2];
    srcA[0] = Qh + (size_t)(bi * 128) * NFEAT;
    srcA[1] = Qh + (size_t)(bj * 128) * NFEAT;

    // 8 x 16B cp.async per thread per stage (2048 chunks of 16B = 32 KB)
    unsigned sdst[8];
    const __half* gsrc[8];
#pragma unroll
    for (int j = 0; j < 8; ++j) {
        int idx = j * 256 + tid;         // 0..2047
        int arr = idx >> 10;             // 0..1
        int rem = idx & 1023;
        int row = rem >> 3;              // 0..127
        int c16 = rem & 7;               // 0..7 (16B units across 128B row)
        sdst[j] = (unsigned)(arr * ARR_S + row * (PAD_S * 2) + c16 * 16);
        gsrc[j] = srcA[arr] + (size_t)row * NFEAT + c16 * 8;
    }

    const int g  = lane >> 3;
    const int rr = lane & 7;
    const int arow = wm * 64 + rr + (g & 1) * 8;
    const int acol = (g >> 1) * 8;
    unsigned a_off[4];
#pragma unroll
    for (int mt = 0; mt < 4; ++mt)
        a_off[mt] = (unsigned)((arow + mt * 16) * (PAD_S * 2) + acol * 2);
    unsigned b_off[2];
#pragma unroll
    for (int np = 0; np < 2; ++np) {
        int brow = wn * 32 + np * 16 + rr + (g & 1) * 8;
        b_off[np] = (unsigned)(brow * (PAD_S * 2) + acol * 2);
    }

    float acc[4][4][4];
#pragma unroll
    for (int i = 0; i < 4; ++i)
#pragma unroll
        for (int j = 0; j < 4; ++j)
#pragma unroll
            for (int k = 0; k < 4; ++k) acc[i][j][k] = 0.0f;

    const int NKC = NFEAT / BKS;   // 128

#pragma unroll
    for (int j = 0; j < 8; ++j)
        cp16(sbase + sdst[j], gsrc[j]);
    CP_COMMIT();

    for (int kc = 0; kc < NKC; ++kc) {
        CP_WAIT(0);
        __syncthreads();

        if (kc + 1 < NKC) {
            const unsigned sb = sbase + ((kc + 1) & 1) * STAGE_S;
            const size_t o = (size_t)(kc + 1) * BKS;
#pragma unroll
            for (int j = 0; j < 8; ++j)
                cp16(sb + sdst[j], gsrc[j] + o);
            CP_COMMIT();
        }

        const unsigned buf = sbase + (kc & 1) * STAGE_S;
#pragma unroll
        for (int kk = 0; kk < BKS; kk += 16) {
            unsigned a[4][4], b[4][2];
#pragma unroll
            for (int mt = 0; mt < 4; ++mt)
                ldsm4(a[mt][0], a[mt][1], a[mt][2], a[mt][3],
                      buf + a_off[mt] + kk * 2);
#pragma unroll
            for (int np = 0; np < 2; ++np) {
                unsigned f0, f1, f2, f3;
                ldsm4(f0, f1, f2, f3, buf + ARR_S + b_off[np] + kk * 2);
                b[2 * np][0] = f0; b[2 * np][1] = f2;
                b[2 * np + 1][0] = f1; b[2 * np + 1][1] = f3;
            }
#pragma unroll
            for (int mt = 0; mt < 4; ++mt)
#pragma unroll
                for (int nt = 0; nt < 4; ++nt)
                    mma_f16(acc[mt][nt], a[mt], b[nt]);
        }
    }

    // ---- writeback: scale by 1/4096, mask diag, store fp16 ----
    const bool diag = (bi == bj);
    const float inv = 1.0f / 4096.0f;
    const int qrow = lane >> 2;
    const int qcol = (lane & 3) * 2;
#pragma unroll
    for (int mt = 0; mt < 4; ++mt) {
#pragma unroll
        for (int nt = 0; nt < 4; ++nt) {
            int row = bi * 128 + wm * 64 + mt * 16 + qrow;
            int col = bj * 128 + wn * 32 + nt * 8 + qcol;
#pragma unroll
            for (int half = 0; half < 2; ++half) {
                int r = row + half * 8;
                float v0 = acc[mt][nt][half * 2 + 0] * inv;
                float v1 = acc[mt][nt][half * 2 + 1] * inv;
                if (diag) {
                    if (col + 0 >= r) v0 = 0.0f;
                    if (col + 1 >= r) v1 = 0.0f;
                }
                __half2 hv; hv.x = __float2half_rn(v0); hv.y = __float2half_rn(v1);
                *(__half2*)(Sh + (size_t)r * T_SEQ + col) = hv;
            }
        }
    }
}

// ============================================================================
// Kernel 4: O = S * V via fp16 HMMA.  A = S (k-contig), B = Vt (k-contig).
// K = (bi+1)*128.  BK=32 double-buffer (as R15).
// ============================================================================
#define BKO       32
#define PAD_O     40
#define ARR_O     (128 * PAD_O * 2)        // 10240
#define STAGE_O   (2 * ARR_O)              // 20480
#define SMEM_O    (2 * STAGE_O)            // 40960

__global__ __launch_bounds__(256, 2) void gemm_out_kernel(float* __restrict__ O) {
    extern __shared__ __align__(128) char smem[];
    const unsigned sbase = smem_u32(smem);

    const int h  = blockIdx.z;
    const int bi = blockIdx.y;
    const int bj = blockIdx.x;
    const __half* __restrict__ Sh = g_S + (size_t)h * T_SEQ * T_SEQ;
    float* __restrict__ Oh = O + (size_t)h * T_SEQ * DV;

    const int tid  = threadIdx.x;
    const int lane = tid & 31;
    const int wid  = tid >> 5;
    const int wm   = wid >> 2;
    const int wn   = wid & 3;

    const __half* srcA[2];
    srcA[0] = Sh + (size_t)(bi * 128) * T_SEQ;
    srcA[1] = g_Vt + (size_t)(bj * 128) * T_SEQ;

    unsigned sdst[4];
    const __half* gsrc[4];
#pragma unroll
    for (int j = 0; j < 4; ++j) {
        int idx = j * 256 + tid;
        int arr = idx >> 9;
        int rem = idx & 511;
        int row = rem >> 2;
        int c16 = rem & 3;
        sdst[j] = (unsigned)(arr * ARR_O + row * (PAD_O * 2) + c16 * 16);
        gsrc[j] = srcA[arr] + (size_t)row * T_SEQ + c16 * 8;
    }

    const int g  = lane >> 3;
    const int rr = lane & 7;
    const int arow = wm * 64 + rr + (g & 1) * 8;
    const int acol = (g >> 1) * 8;
    unsigned a_off[4];
#pragma unroll
    for (int mt = 0; mt < 4; ++mt)
        a_off[mt] = (unsigned)((arow + mt * 16) * (PAD_O * 2) + acol * 2);
    unsigned b_off[2];
#pragma unroll
    for (int np = 0; np < 2; ++np) {
        int brow = wn * 32 + np * 16 + rr + (g & 1) * 8;
        b_off[np] = (unsigned)(brow * (PAD_O * 2) + acol * 2);
    }

    float acc[4][4][4];
#pragma unroll
    for (int i = 0; i < 4; ++i)
#pragma unroll
        for (int j = 0; j < 4; ++j)
#pragma unroll
            for (int k = 0; k < 4; ++k) acc[i][j][k] = 0.0f;

    const int NKC = (bi + 1) * (128 / BKO);

#pragma unroll
    for (int j = 0; j < 4; ++j)
        cp16(sbase + sdst[j], gsrc[j]);
    CP_COMMIT();

    for (int kc = 0; kc < NKC; ++kc) {
        CP_WAIT(0);
        __syncthreads();

        if (kc + 1 < NKC) {
            const unsigned sb = sbase + ((kc + 1) & 1) * STAGE_O;
            const size_t o = (size_t)(kc + 1) * BKO;
#pragma unroll
            for (int j = 0; j < 4; ++j)
                cp16(sb + sdst[j], gsrc[j] + o);
            CP_COMMIT();
        }

        const unsigned buf = sbase + (kc & 1) * STAGE_O;
#pragma unroll
        for (int kk = 0; kk < BKO; kk += 16) {
            unsigned a[4][4], b[4][2];
#pragma unroll
            for (int mt = 0; mt < 4; ++mt)
                ldsm4(a[mt][0], a[mt][1], a[mt][2], a[mt][3],
                      buf + a_off[mt] + kk * 2);
#pragma unroll
            for (int np = 0; np < 2; ++np) {
                unsigned f0, f1, f2, f3;
                ldsm4(f0, f1, f2, f3, buf + ARR_O + b_off[np] + kk * 2);
                b[2 * np][0] = f0; b[2 * np][1] = f2;
                b[2 * np + 1][0] = f1; b[2 * np + 1][1] = f3;
            }
#pragma unroll
            for (int mt = 0; mt < 4; ++mt)
#pragma unroll
                for (int nt = 0; nt < 4; ++nt)
                    mma_f16(acc[mt][nt], a[mt], b[nt]);
        }
    }

    const int qrow = lane >> 2;
    const int qcol = (lane & 3) * 2;
#pragma unroll
    for (int mt = 0; mt < 4; ++mt) {
#pragma unroll
        for (int nt = 0; nt < 4; ++nt) {
            int row = bi * 128 + wm * 64 + mt * 16 + qrow;
            int col = bj * 128 + wn * 32 + nt * 8 + qcol;
#pragma unroll
            for (int half = 0; half < 2; ++half) {
                int r = row + half * 8;
                *(float2*)(Oh + (size_t)r * DV + col) =
                    make_float2(acc[mt][nt][half * 2 + 0], acc[mt][nt][half * 2 + 1]);
            }
        }
    }
}

// ============================================================================
extern "C" void kernel_launch(void* const* d_in, const int* in_sizes, int n_in,
                              void* d_out, int out_size) {
    const float* Q = (const float*)d_in[0];
    const float* V = (const float*)d_in[1];
    float* O = (float*)d_out;

    static bool attr_set = false;
    if (!attr_set) {
        cudaFuncSetAttribute(gemm_scores_kernel,
                             cudaFuncAttributeMaxDynamicSharedMemorySize, SMEM_S);
        cudaFuncSetAttribute(gemm_out_kernel,
                             cudaFuncAttributeMaxDynamicSharedMemorySize, SMEM_O);
        attr_set = true;
    }

    const int tab_elems  = T_SEQ * HALF_N;
    const int rope_pos   = T_SEQ * HALF_N;   // one thread covers 4 heads

    freq_kernel<<<(HALF_N + 255) / 256, 256>>>();
    build_tab_kernel<<<(tab_elems + 255) / 256, 256>>>();
    rope_kernel<<<(rope_pos + 255) / 256, 256>>>(Q);
    vt_kernel<<<dim3(T_SEQ / 32, DV / 32), 256>>>(V);
    gemm_scores_kernel<<<dim3(136, NH), 256, SMEM_S>>>();
    gemm_out_kernel<<<dim3(DV / 128, T_SEQ / 128, NH), 256, SMEM_O>>>(O);
}